// round 1
// baseline (speedup 1.0000x reference)
#include <cuda_runtime.h>
#include <math.h>

#define B_SZ   4
#define S_LEN  2048
#define NH     16
#define HD     128
#define DM     2048                 // model dim == NH*HD
#define M_TOT  (B_SZ * S_LEN)       // 8192 tokens

// Scratch buffers (allocation-free: __device__ globals)
__device__ __align__(128) float g_q[(size_t)M_TOT * DM];
__device__ __align__(128) float g_k[(size_t)M_TOT * DM];
__device__ __align__(128) float g_v[(size_t)M_TOT * DM];
__device__ __align__(128) float g_attn[(size_t)M_TOT * DM];

// ---------------------------------------------------------------------------
// SGEMM: C[M,N] = A[M,K] * B[K,N], fp32, 128x128x16 tile, 256 thr, 8x8 micro
// M,N,K all multiples of 128/16 here (8192 x 2048 x 2048) — no bounds checks.
// ---------------------------------------------------------------------------
__global__ __launch_bounds__(256) void sgemm128(
    const float* __restrict__ A, const float* __restrict__ B,
    float* __restrict__ C, int M, int N, int K)
{
    __shared__ float As[16][128];   // transposed A tile: As[k][m]
    __shared__ float Bs[16][128];   // Bs[k][n]

    const int tid = threadIdx.x;
    const int tx  = tid & 15;       // 0..15  -> 8 cols each
    const int ty  = tid >> 4;       // 0..15  -> 8 rows each
    const int bx  = blockIdx.x;     // N tile
    const int by  = blockIdx.y;     // M tile

    const float* Ab = A + (size_t)by * 128 * K;
    const float* Bb = B + (size_t)bx * 128;

    float acc[8][8];
    #pragma unroll
    for (int i = 0; i < 8; i++)
        #pragma unroll
        for (int j = 0; j < 8; j++) acc[i][j] = 0.f;

    for (int kt = 0; kt < K; kt += 16) {
        // Load A tile 128x16 (512 float4, 2 per thread), store transposed
        #pragma unroll
        for (int i = 0; i < 2; i++) {
            int idx = tid + i * 256;         // 0..511
            int row = idx >> 2;              // 4 float4 per row of 16
            int c4  = idx & 3;
            float4 v = *(const float4*)(Ab + (size_t)row * K + kt + c4 * 4);
            As[c4 * 4 + 0][row] = v.x;
            As[c4 * 4 + 1][row] = v.y;
            As[c4 * 4 + 2][row] = v.z;
            As[c4 * 4 + 3][row] = v.w;
        }
        // Load B tile 16x128
        #pragma unroll
        for (int i = 0; i < 2; i++) {
            int idx = tid + i * 256;
            int row = idx >> 5;              // 32 float4 per row of 128
            int c4  = idx & 31;
            *(float4*)(&Bs[row][c4 * 4]) =
                *(const float4*)(Bb + (size_t)(kt + row) * N + c4 * 4);
        }
        __syncthreads();

        #pragma unroll
        for (int kk = 0; kk < 16; kk++) {
            float a[8], b[8];
            *(float4*)(a)     = *(float4*)(&As[kk][ty * 8]);
            *(float4*)(a + 4) = *(float4*)(&As[kk][ty * 8 + 4]);
            *(float4*)(b)     = *(float4*)(&Bs[kk][tx * 8]);
            *(float4*)(b + 4) = *(float4*)(&Bs[kk][tx * 8 + 4]);
            #pragma unroll
            for (int i = 0; i < 8; i++)
                #pragma unroll
                for (int j = 0; j < 8; j++)
                    acc[i][j] = fmaf(a[i], b[j], acc[i][j]);
        }
        __syncthreads();
    }

    #pragma unroll
    for (int i = 0; i < 8; i++) {
        size_t r = (size_t)(by * 128 + ty * 8 + i) * N + bx * 128 + tx * 8;
        *(float4*)(C + r)     = make_float4(acc[i][0], acc[i][1], acc[i][2], acc[i][3]);
        *(float4*)(C + r + 4) = make_float4(acc[i][4], acc[i][5], acc[i][6], acc[i][7]);
    }
}

// ---------------------------------------------------------------------------
// LLaMA interleaved RoPE on q and k; q additionally scaled by 1/sqrt(H).
// One thread per (token, head, pair).
// ---------------------------------------------------------------------------
__global__ void rope_kernel(float* __restrict__ q, float* __restrict__ k, int total)
{
    int idx = blockIdx.x * blockDim.x + threadIdx.x;
    if (idx >= total) return;
    int pair = idx & 63;             // i in [0,64)
    int n    = (idx >> 6) & (NH - 1);
    int m    = idx >> 10;            // token index
    int s    = m & (S_LEN - 1);      // position within sequence

    float fraction  = (2.0f * (float)pair) / (float)HD;
    // timescale = 10000^fraction  (accurate exp2)
    float timescale = exp2f(fraction * 13.287712379549449f); // log2(10000)
    float ang = (float)s / timescale;
    float sv, cv;
    sincosf(ang, &sv, &cv);

    size_t base = (size_t)m * DM + (size_t)n * HD + pair * 2;
    const float qs = 0.08838834764831845f; // 1/sqrt(128)

    float q1 = q[base], q2 = q[base + 1];
    q[base]     = (q1 * cv - q2 * sv) * qs;
    q[base + 1] = (q2 * cv + q1 * sv) * qs;

    float k1 = k[base], k2 = k[base + 1];
    k[base]     = k1 * cv - k2 * sv;
    k[base + 1] = k2 * cv + k1 * sv;
}

// ---------------------------------------------------------------------------
// Causal flash attention, fp32. One CTA per (b, n, 64-row q tile).
// Online softmax over 64-row K tiles. 256 threads.
// ---------------------------------------------------------------------------
struct FlashSmem {
    float Qs[64 * 128];      // unswizzled (broadcast reads only)
    float Ks[64 * 128];      // XOR-swizzled float4 columns: c4' = c4 ^ (row>>2)
    float Vs[64 * 128];      // unswizzled
    float Ss[64 * 65];       // padded stride 65 (conflict-free softmax)
    float mrow[64];
    float lrow[64];
    float srow[64];
};

__global__ __launch_bounds__(256) void flash_kernel(
    const float* __restrict__ Q, const float* __restrict__ K,
    const float* __restrict__ V, float* __restrict__ O)
{
    extern __shared__ __align__(16) float smem_raw[];
    FlashSmem* sm = (FlashSmem*)smem_raw;

    const int tid = threadIdx.x;
    const int qt  = blockIdx.x;
    const int n   = blockIdx.y;
    const int b   = blockIdx.z;
    const int q0  = qt * 64;
    const size_t head_off = (size_t)n * HD;

    // Load Q tile (64x128), coalesced
    #pragma unroll
    for (int i = 0; i < 8; i++) {
        int idx = tid + i * 256;            // float4 index 0..2047
        int row = idx >> 5, c4 = idx & 31;
        size_t g = ((size_t)(b * S_LEN + q0 + row)) * DM + head_off + c4 * 4;
        *(float4*)(&sm->Qs[row * 128 + c4 * 4]) = *(const float4*)(Q + g);
    }
    if (tid < 64) { sm->mrow[tid] = -1e30f; sm->lrow[tid] = 0.f; }

    float acc[4][8];
    #pragma unroll
    for (int i = 0; i < 4; i++)
        #pragma unroll
        for (int j = 0; j < 8; j++) acc[i][j] = 0.f;

    const int r0  = (tid >> 4) * 4;   // O/S row group (4 rows)
    const int c0  = (tid & 15) * 8;   // O col group (8 cols)
    const int cs0 = (tid & 15) * 4;   // S col group (4 cols)

    __syncthreads();

    for (int kt = 0; kt <= qt; kt++) {
        const int k0 = kt * 64;

        // Load K (swizzled) and V tiles
        #pragma unroll
        for (int i = 0; i < 8; i++) {
            int idx = tid + i * 256;
            int row = idx >> 5, c4 = idx & 31;
            size_t g = ((size_t)(b * S_LEN + k0 + row)) * DM + head_off + c4 * 4;
            int c4sw = c4 ^ (row >> 2);
            *(float4*)(&sm->Ks[row * 128 + c4sw * 4]) = *(const float4*)(K + g);
            *(float4*)(&sm->Vs[row * 128 + c4   * 4]) = *(const float4*)(V + g);
        }
        __syncthreads();

        // S = Q K^T  (4x4 per thread)
        float s[4][4];
        #pragma unroll
        for (int i = 0; i < 4; i++)
            #pragma unroll
            for (int j = 0; j < 4; j++) s[i][j] = 0.f;

        #pragma unroll
        for (int h4 = 0; h4 < 32; h4++) {
            float4 qv[4], kv[4];
            #pragma unroll
            for (int i = 0; i < 4; i++) {
                qv[i] = *(float4*)(&sm->Qs[(r0 + i) * 128 + h4 * 4]);
                int krow = cs0 + i;
                kv[i] = *(float4*)(&sm->Ks[krow * 128 + (h4 ^ (krow >> 2)) * 4]);
            }
            #pragma unroll
            for (int i = 0; i < 4; i++)
                #pragma unroll
                for (int j = 0; j < 4; j++)
                    s[i][j] += qv[i].x * kv[j].x + qv[i].y * kv[j].y
                             + qv[i].z * kv[j].z + qv[i].w * kv[j].w;
        }

        const bool diag = (kt == qt);
        #pragma unroll
        for (int i = 0; i < 4; i++)
            #pragma unroll
            for (int j = 0; j < 4; j++) {
                float val = s[i][j];
                if (diag && (k0 + cs0 + j) > (q0 + r0 + i)) val = -1e30f;
                sm->Ss[(r0 + i) * 65 + cs0 + j] = val;
            }
        __syncthreads();

        // Online softmax row update (one thread per row)
        if (tid < 64) {
            int r = tid;
            float mold = sm->mrow[r];
            float mx = mold;
            #pragma unroll 8
            for (int c = 0; c < 64; c++) mx = fmaxf(mx, sm->Ss[r * 65 + c]);
            float scale = __expf(mold - mx);
            float sum = 0.f;
            #pragma unroll 8
            for (int c = 0; c < 64; c++) {
                float p = __expf(sm->Ss[r * 65 + c] - mx);
                sm->Ss[r * 65 + c] = p;
                sum += p;
            }
            sm->mrow[r] = mx;
            sm->lrow[r] = sm->lrow[r] * scale + sum;
            sm->srow[r] = scale;
        }
        __syncthreads();

        // Rescale acc, accumulate P*V
        float scl[4];
        #pragma unroll
        for (int i = 0; i < 4; i++) scl[i] = sm->srow[r0 + i];
        #pragma unroll
        for (int i = 0; i < 4; i++)
            #pragma unroll
            for (int j = 0; j < 8; j++) acc[i][j] *= scl[i];

        #pragma unroll 4
        for (int kk = 0; kk < 64; kk++) {
            float p[4];
            #pragma unroll
            for (int i = 0; i < 4; i++) p[i] = sm->Ss[(r0 + i) * 65 + kk];
            float4 v0 = *(float4*)(&sm->Vs[kk * 128 + c0]);
            float4 v1 = *(float4*)(&sm->Vs[kk * 128 + c0 + 4]);
            #pragma unroll
            for (int i = 0; i < 4; i++) {
                acc[i][0] = fmaf(p[i], v0.x, acc[i][0]);
                acc[i][1] = fmaf(p[i], v0.y, acc[i][1]);
                acc[i][2] = fmaf(p[i], v0.z, acc[i][2]);
                acc[i][3] = fmaf(p[i], v0.w, acc[i][3]);
                acc[i][4] = fmaf(p[i], v1.x, acc[i][4]);
                acc[i][5] = fmaf(p[i], v1.y, acc[i][5]);
                acc[i][6] = fmaf(p[i], v1.z, acc[i][6]);
                acc[i][7] = fmaf(p[i], v1.w, acc[i][7]);
            }
        }
        __syncthreads();
    }

    // Normalize and write out
    #pragma unroll
    for (int i = 0; i < 4; i++) {
        float inv = 1.0f / sm->lrow[r0 + i];
        size_t g = ((size_t)(b * S_LEN + q0 + r0 + i)) * DM + head_off + c0;
        *(float4*)(O + g) =
            make_float4(acc[i][0] * inv, acc[i][1] * inv, acc[i][2] * inv, acc[i][3] * inv);
        *(float4*)(O + g + 4) =
            make_float4(acc[i][4] * inv, acc[i][5] * inv, acc[i][6] * inv, acc[i][7] * inv);
    }
}

// ---------------------------------------------------------------------------
extern "C" void kernel_launch(void* const* d_in, const int* in_sizes, int n_in,
                              void* d_out, int out_size)
{
    const float* x  = (const float*)d_in[0];
    const float* wq = (const float*)d_in[1];
    const float* wk = (const float*)d_in[2];
    const float* wv = (const float*)d_in[3];
    const float* wo = (const float*)d_in[4];
    float* out = (float*)d_out;

    float *q, *k, *v, *attn;
    cudaGetSymbolAddress((void**)&q,    g_q);
    cudaGetSymbolAddress((void**)&k,    g_k);
    cudaGetSymbolAddress((void**)&v,    g_v);
    cudaGetSymbolAddress((void**)&attn, g_attn);

    dim3 ggrid(DM / 128, M_TOT / 128);

    // QKV projections
    sgemm128<<<ggrid, 256>>>(x, wq, q, M_TOT, DM, DM);
    sgemm128<<<ggrid, 256>>>(x, wk, k, M_TOT, DM, DM);
    sgemm128<<<ggrid, 256>>>(x, wv, v, M_TOT, DM, DM);

    // RoPE + q scaling
    int total_pairs = M_TOT * NH * (HD / 2);
    rope_kernel<<<(total_pairs + 255) / 256, 256>>>(q, k, total_pairs);

    // Causal flash attention
    size_t smem = sizeof(FlashSmem);
    cudaFuncSetAttribute(flash_kernel, cudaFuncAttributeMaxDynamicSharedMemorySize,
                         (int)smem);
    dim3 fgrid(S_LEN / 64, NH, B_SZ);
    flash_kernel<<<fgrid, 256, smem>>>(q, k, v, attn);

    // Output projection
    sgemm128<<<ggrid, 256>>>(attn, wo, out, M_TOT, DM, DM);
}

// round 3
// speedup vs baseline: 1.6373x; 1.6373x over previous
#include <cuda_runtime.h>
#include <cuda_bf16.h>
#include <cstdint>
#include <math.h>

#define B_SZ   4
#define S_LEN  2048
#define NH     16
#define HD     128
#define DM     2048
#define M_TOT  (B_SZ * S_LEN)       // 8192 tokens

// Scratch (allocation-free: __device__ globals)
__device__ __align__(128) float g_q[(size_t)M_TOT * DM];
__device__ __align__(128) float g_k[(size_t)M_TOT * DM];
__device__ __align__(128) float g_v[(size_t)M_TOT * DM];
__device__ __align__(128) float g_attn[(size_t)M_TOT * DM];
__device__ __align__(128) float g_wt[4][(size_t)DM * DM];   // transposed weights

// ---------------------------------------------------------------------------
// Transpose: out[N,K] = in[K,N], 2048x2048
// ---------------------------------------------------------------------------
__global__ __launch_bounds__(256) void transpose2048(
    const float* __restrict__ in, float* __restrict__ out)
{
    __shared__ float t[32][33];
    int x = blockIdx.x * 32 + threadIdx.x;
    int y = blockIdx.y * 32 + threadIdx.y;
    #pragma unroll
    for (int i = 0; i < 4; i++)
        t[threadIdx.y + i * 8][threadIdx.x] = in[(size_t)(y + i * 8) * DM + x];
    __syncthreads();
    x = blockIdx.y * 32 + threadIdx.x;
    y = blockIdx.x * 32 + threadIdx.y;
    #pragma unroll
    for (int i = 0; i < 4; i++)
        out[(size_t)(y + i * 8) * DM + x] = t[threadIdx.x][threadIdx.y + i * 8];
}

// ---------------------------------------------------------------------------
// bf16-split tensor-core GEMM: C[M,N] = A[M,K] * Bt[N,K]^T  (fp32 in/out)
// Split a = a_hi + a_lo (bf16), compute hi*hi + hi*lo + lo*hi via
// mma.sync.m16n8k16.bf16 with fp32 accumulators.
// Tile 128x128, K-chunk 32, 256 threads (8 warps, 2x4), warp tile 64x32.
// ---------------------------------------------------------------------------
#define KCHUNK  32
#define APAD    40                      // smem row stride in elements
#define TILE_EL (128 * APAD)            // 5120 elements per array
#define GEMM_SMEM_BYTES (2 /*buf*/ * 4 /*Ah,Al,Bh,Bl*/ * TILE_EL * 2)

__device__ __forceinline__ uint32_t pack_bf2(__nv_bfloat16 a, __nv_bfloat16 b) {
    __nv_bfloat162 t = __halves2bfloat162(a, b);   // a -> low, b -> high
    return *reinterpret_cast<uint32_t*>(&t);
}

#define MMA16816(d, a, b)                                                    \
    asm volatile(                                                            \
        "mma.sync.aligned.m16n8k16.row.col.f32.bf16.bf16.f32 "               \
        "{%0,%1,%2,%3}, {%4,%5,%6,%7}, {%8,%9}, {%0,%1,%2,%3};"              \
        : "+f"((d)[0]), "+f"((d)[1]), "+f"((d)[2]), "+f"((d)[3])             \
        : "r"((a)[0]), "r"((a)[1]), "r"((a)[2]), "r"((a)[3]),                \
          "r"((b)[0]), "r"((b)[1]))

__device__ __forceinline__ void cvt_store_pair(
    __nv_bfloat16* __restrict__ H, __nv_bfloat16* __restrict__ L,
    int r, int c4, float4 v)
{
    __nv_bfloat16 hx = __float2bfloat16(v.x);
    __nv_bfloat16 hy = __float2bfloat16(v.y);
    __nv_bfloat16 hz = __float2bfloat16(v.z);
    __nv_bfloat16 hw = __float2bfloat16(v.w);
    __nv_bfloat16 lx = __float2bfloat16(v.x - __bfloat162float(hx));
    __nv_bfloat16 ly = __float2bfloat16(v.y - __bfloat162float(hy));
    __nv_bfloat16 lz = __float2bfloat16(v.z - __bfloat162float(hz));
    __nv_bfloat16 lw = __float2bfloat16(v.w - __bfloat162float(hw));
    int off = r * APAD + c4 * 4;
    *(uint2*)(H + off) = make_uint2(pack_bf2(hx, hy), pack_bf2(hz, hw));
    *(uint2*)(L + off) = make_uint2(pack_bf2(lx, ly), pack_bf2(lz, lw));
}

__global__ __launch_bounds__(256) void gemm_bf16x3(
    const float* __restrict__ A, const float* __restrict__ Bt,
    float* __restrict__ C, int M, int N, int K)
{
    extern __shared__ __align__(16) __nv_bfloat16 sm[];

    const int tid  = threadIdx.x;
    const int lane = tid & 31;
    const int wid  = tid >> 5;
    const int warpM = wid & 1;           // 2 warps along M
    const int warpN = wid >> 1;          // 4 warps along N
    const int n0 = blockIdx.x * 128;
    const int m0 = blockIdx.y * 128;

    // Loader geometry: each thread loads 4 float4 per tile per operand
    const int row_ = tid >> 3;           // 0..31 (+i*32)
    const int c_   = tid & 7;            // float4 column within 32-col chunk
    const float* Ab = A  + (size_t)(m0 + row_) * K + c_ * 4;
    const float* Bb = Bt + (size_t)(n0 + row_) * K + c_ * 4;

    float acc[4][4][4];
    #pragma unroll
    for (int mt = 0; mt < 4; mt++)
        #pragma unroll
        for (int nt = 0; nt < 4; nt++)
            #pragma unroll
            for (int e = 0; e < 4; e++) acc[mt][nt][e] = 0.f;

    float4 ra[4], rb[4];
    #pragma unroll
    for (int i = 0; i < 4; i++) {
        ra[i] = *(const float4*)(Ab + (size_t)(i * 32) * K);
        rb[i] = *(const float4*)(Bb + (size_t)(i * 32) * K);
    }

    const int NK = K / KCHUNK;
    const int mrow = lane >> 2;          // 0..7
    const int kcol = (lane & 3) * 2;     // 0,2,4,6

    for (int kt = 0; kt < NK; kt++) {
        const int p = kt & 1;
        __nv_bfloat16* Ah = sm + (size_t)(p * 4 + 0) * TILE_EL;
        __nv_bfloat16* Al = sm + (size_t)(p * 4 + 1) * TILE_EL;
        __nv_bfloat16* Bh = sm + (size_t)(p * 4 + 2) * TILE_EL;
        __nv_bfloat16* Bl = sm + (size_t)(p * 4 + 3) * TILE_EL;

        #pragma unroll
        for (int i = 0; i < 4; i++) {
            cvt_store_pair(Ah, Al, row_ + i * 32, c_, ra[i]);
            cvt_store_pair(Bh, Bl, row_ + i * 32, c_, rb[i]);
        }
        __syncthreads();

        if (kt + 1 < NK) {
            #pragma unroll
            for (int i = 0; i < 4; i++) {
                ra[i] = *(const float4*)(Ab + (size_t)(i * 32) * K + (kt + 1) * KCHUNK);
                rb[i] = *(const float4*)(Bb + (size_t)(i * 32) * K + (kt + 1) * KCHUNK);
            }
        }

        #pragma unroll
        for (int ks = 0; ks < 2; ks++) {
            const int kb = ks * 16 + kcol;
            uint32_t ah[4][4], al[4][4], bh[4][2], bl[4][2];
            #pragma unroll
            for (int mt = 0; mt < 4; mt++) {
                int r = warpM * 64 + mt * 16 + mrow;
                ah[mt][0] = *(const uint32_t*)(Ah + r * APAD + kb);
                ah[mt][1] = *(const uint32_t*)(Ah + (r + 8) * APAD + kb);
                ah[mt][2] = *(const uint32_t*)(Ah + r * APAD + kb + 8);
                ah[mt][3] = *(const uint32_t*)(Ah + (r + 8) * APAD + kb + 8);
                al[mt][0] = *(const uint32_t*)(Al + r * APAD + kb);
                al[mt][1] = *(const uint32_t*)(Al + (r + 8) * APAD + kb);
                al[mt][2] = *(const uint32_t*)(Al + r * APAD + kb + 8);
                al[mt][3] = *(const uint32_t*)(Al + (r + 8) * APAD + kb + 8);
            }
            #pragma unroll
            for (int nt = 0; nt < 4; nt++) {
                int c = warpN * 32 + nt * 8 + mrow;
                bh[nt][0] = *(const uint32_t*)(Bh + c * APAD + kb);
                bh[nt][1] = *(const uint32_t*)(Bh + c * APAD + kb + 8);
                bl[nt][0] = *(const uint32_t*)(Bl + c * APAD + kb);
                bl[nt][1] = *(const uint32_t*)(Bl + c * APAD + kb + 8);
            }
            #pragma unroll
            for (int mt = 0; mt < 4; mt++)
                #pragma unroll
                for (int nt = 0; nt < 4; nt++) {
                    MMA16816(acc[mt][nt], ah[mt], bh[nt]);
                    MMA16816(acc[mt][nt], ah[mt], bl[nt]);
                    MMA16816(acc[mt][nt], al[mt], bh[nt]);
                }
        }
        __syncthreads();
    }

    // Epilogue: fp32 stores straight from accumulators
    #pragma unroll
    for (int mt = 0; mt < 4; mt++) {
        #pragma unroll
        for (int nt = 0; nt < 4; nt++) {
            int row = m0 + warpM * 64 + mt * 16 + mrow;
            int col = n0 + warpN * 32 + nt * 8 + kcol;
            *(float2*)(C + (size_t)row * N + col) =
                make_float2(acc[mt][nt][0], acc[mt][nt][1]);
            *(float2*)(C + (size_t)(row + 8) * N + col) =
                make_float2(acc[mt][nt][2], acc[mt][nt][3]);
        }
    }
}

// ---------------------------------------------------------------------------
// LLaMA interleaved RoPE; q additionally scaled by 1/sqrt(H).
// ---------------------------------------------------------------------------
__global__ void rope_kernel(float* __restrict__ q, float* __restrict__ k, int total)
{
    int idx = blockIdx.x * blockDim.x + threadIdx.x;
    if (idx >= total) return;
    int pair = idx & 63;
    int n    = (idx >> 6) & (NH - 1);
    int m    = idx >> 10;
    int s    = m & (S_LEN - 1);

    float fraction  = (2.0f * (float)pair) / (float)HD;
    float timescale = exp2f(fraction * 13.287712379549449f); // log2(10000)
    float ang = (float)s / timescale;
    float sv, cv;
    sincosf(ang, &sv, &cv);

    size_t base = (size_t)m * DM + (size_t)n * HD + pair * 2;
    const float qs = 0.08838834764831845f; // 1/sqrt(128)

    float q1 = q[base], q2 = q[base + 1];
    q[base]     = (q1 * cv - q2 * sv) * qs;
    q[base + 1] = (q2 * cv + q1 * sv) * qs;

    float k1 = k[base], k2 = k[base + 1];
    k[base]     = k1 * cv - k2 * sv;
    k[base + 1] = k2 * cv + k1 * sv;
}

// ---------------------------------------------------------------------------
// Causal flash attention, fp32 SIMT (unchanged from R1).
// ---------------------------------------------------------------------------
struct FlashSmem {
    float Qs[64 * 128];
    float Ks[64 * 128];
    float Vs[64 * 128];
    float Ss[64 * 65];
    float mrow[64];
    float lrow[64];
    float srow[64];
};

__global__ __launch_bounds__(256) void flash_kernel(
    const float* __restrict__ Q, const float* __restrict__ K,
    const float* __restrict__ V, float* __restrict__ O)
{
    extern __shared__ __align__(16) float smem_raw[];
    FlashSmem* sm = (FlashSmem*)smem_raw;

    const int tid = threadIdx.x;
    const int qt  = blockIdx.x;
    const int n   = blockIdx.y;
    const int b   = blockIdx.z;
    const int q0  = qt * 64;
    const size_t head_off = (size_t)n * HD;

    #pragma unroll
    for (int i = 0; i < 8; i++) {
        int idx = tid + i * 256;
        int row = idx >> 5, c4 = idx & 31;
        size_t g = ((size_t)(b * S_LEN + q0 + row)) * DM + head_off + c4 * 4;
        *(float4*)(&sm->Qs[row * 128 + c4 * 4]) = *(const float4*)(Q + g);
    }
    if (tid < 64) { sm->mrow[tid] = -1e30f; sm->lrow[tid] = 0.f; }

    float acc[4][8];
    #pragma unroll
    for (int i = 0; i < 4; i++)
        #pragma unroll
        for (int j = 0; j < 8; j++) acc[i][j] = 0.f;

    const int r0  = (tid >> 4) * 4;
    const int c0  = (tid & 15) * 8;
    const int cs0 = (tid & 15) * 4;

    __syncthreads();

    for (int kt = 0; kt <= qt; kt++) {
        const int k0 = kt * 64;

        #pragma unroll
        for (int i = 0; i < 8; i++) {
            int idx = tid + i * 256;
            int row = idx >> 5, c4 = idx & 31;
            size_t g = ((size_t)(b * S_LEN + k0 + row)) * DM + head_off + c4 * 4;
            int c4sw = c4 ^ (row >> 2);
            *(float4*)(&sm->Ks[row * 128 + c4sw * 4]) = *(const float4*)(K + g);
            *(float4*)(&sm->Vs[row * 128 + c4   * 4]) = *(const float4*)(V + g);
        }
        __syncthreads();

        float s[4][4];
        #pragma unroll
        for (int i = 0; i < 4; i++)
            #pragma unroll
            for (int j = 0; j < 4; j++) s[i][j] = 0.f;

        #pragma unroll
        for (int h4 = 0; h4 < 32; h4++) {
            float4 qv[4], kv[4];
            #pragma unroll
            for (int i = 0; i < 4; i++) {
                qv[i] = *(float4*)(&sm->Qs[(r0 + i) * 128 + h4 * 4]);
                int krow = cs0 + i;
                kv[i] = *(float4*)(&sm->Ks[krow * 128 + (h4 ^ (krow >> 2)) * 4]);
            }
            #pragma unroll
            for (int i = 0; i < 4; i++)
                #pragma unroll
                for (int j = 0; j < 4; j++)
                    s[i][j] += qv[i].x * kv[j].x + qv[i].y * kv[j].y
                             + qv[i].z * kv[j].z + qv[i].w * kv[j].w;
        }

        const bool diag = (kt == qt);
        #pragma unroll
        for (int i = 0; i < 4; i++)
            #pragma unroll
            for (int j = 0; j < 4; j++) {
                float val = s[i][j];
                if (diag && (k0 + cs0 + j) > (q0 + r0 + i)) val = -1e30f;
                sm->Ss[(r0 + i) * 65 + cs0 + j] = val;
            }
        __syncthreads();

        if (tid < 64) {
            int r = tid;
            float mold = sm->mrow[r];
            float mx = mold;
            #pragma unroll 8
            for (int c = 0; c < 64; c++) mx = fmaxf(mx, sm->Ss[r * 65 + c]);
            float scale = __expf(mold - mx);
            float sum = 0.f;
            #pragma unroll 8
            for (int c = 0; c < 64; c++) {
                float p = __expf(sm->Ss[r * 65 + c] - mx);
                sm->Ss[r * 65 + c] = p;
                sum += p;
            }
            sm->mrow[r] = mx;
            sm->lrow[r] = sm->lrow[r] * scale + sum;
            sm->srow[r] = scale;
        }
        __syncthreads();

        float scl[4];
        #pragma unroll
        for (int i = 0; i < 4; i++) scl[i] = sm->srow[r0 + i];
        #pragma unroll
        for (int i = 0; i < 4; i++)
            #pragma unroll
            for (int j = 0; j < 8; j++) acc[i][j] *= scl[i];

        #pragma unroll 4
        for (int kk = 0; kk < 64; kk++) {
            float p[4];
            #pragma unroll
            for (int i = 0; i < 4; i++) p[i] = sm->Ss[(r0 + i) * 65 + kk];
            float4 v0 = *(float4*)(&sm->Vs[kk * 128 + c0]);
            float4 v1 = *(float4*)(&sm->Vs[kk * 128 + c0 + 4]);
            #pragma unroll
            for (int i = 0; i < 4; i++) {
                acc[i][0] = fmaf(p[i], v0.x, acc[i][0]);
                acc[i][1] = fmaf(p[i], v0.y, acc[i][1]);
                acc[i][2] = fmaf(p[i], v0.z, acc[i][2]);
                acc[i][3] = fmaf(p[i], v0.w, acc[i][3]);
                acc[i][4] = fmaf(p[i], v1.x, acc[i][4]);
                acc[i][5] = fmaf(p[i], v1.y, acc[i][5]);
                acc[i][6] = fmaf(p[i], v1.z, acc[i][6]);
                acc[i][7] = fmaf(p[i], v1.w, acc[i][7]);
            }
        }
        __syncthreads();
    }

    #pragma unroll
    for (int i = 0; i < 4; i++) {
        float inv = 1.0f / sm->lrow[r0 + i];
        size_t g = ((size_t)(b * S_LEN + q0 + r0 + i)) * DM + head_off + c0;
        *(float4*)(O + g) =
            make_float4(acc[i][0] * inv, acc[i][1] * inv, acc[i][2] * inv, acc[i][3] * inv);
        *(float4*)(O + g + 4) =
            make_float4(acc[i][4] * inv, acc[i][5] * inv, acc[i][6] * inv, acc[i][7] * inv);
    }
}

// ---------------------------------------------------------------------------
extern "C" void kernel_launch(void* const* d_in, const int* in_sizes, int n_in,
                              void* d_out, int out_size)
{
    const float* x  = (const float*)d_in[0];
    const float* wq = (const float*)d_in[1];
    const float* wk = (const float*)d_in[2];
    const float* wv = (const float*)d_in[3];
    const float* wo = (const float*)d_in[4];
    float* out = (float*)d_out;

    float *q, *k, *v, *attn, *wt;
    cudaGetSymbolAddress((void**)&q,    g_q);
    cudaGetSymbolAddress((void**)&k,    g_k);
    cudaGetSymbolAddress((void**)&v,    g_v);
    cudaGetSymbolAddress((void**)&attn, g_attn);
    cudaGetSymbolAddress((void**)&wt,   g_wt);
    float* wqt = wt;
    float* wkt = wt + (size_t)DM * DM;
    float* wvt = wt + 2 * (size_t)DM * DM;
    float* wot = wt + 3 * (size_t)DM * DM;

    // Transpose weights -> [N, K]
    dim3 tgrid(DM / 32, DM / 32), tblk(32, 8);
    transpose2048<<<tgrid, tblk>>>(wq, wqt);
    transpose2048<<<tgrid, tblk>>>(wk, wkt);
    transpose2048<<<tgrid, tblk>>>(wv, wvt);
    transpose2048<<<tgrid, tblk>>>(wo, wot);

    // bf16-split tensor-core GEMMs
    cudaFuncSetAttribute(gemm_bf16x3, cudaFuncAttributeMaxDynamicSharedMemorySize,
                         GEMM_SMEM_BYTES);
    dim3 ggrid(DM / 128, M_TOT / 128);
    gemm_bf16x3<<<ggrid, 256, GEMM_SMEM_BYTES>>>(x, wqt, q, M_TOT, DM, DM);
    gemm_bf16x3<<<ggrid, 256, GEMM_SMEM_BYTES>>>(x, wkt, k, M_TOT, DM, DM);
    gemm_bf16x3<<<ggrid, 256, GEMM_SMEM_BYTES>>>(x, wvt, v, M_TOT, DM, DM);

    // RoPE + q scaling
    int total_pairs = M_TOT * NH * (HD / 2);
    rope_kernel<<<(total_pairs + 255) / 256, 256>>>(q, k, total_pairs);

    // Causal flash attention
    size_t smem = sizeof(FlashSmem);
    cudaFuncSetAttribute(flash_kernel, cudaFuncAttributeMaxDynamicSharedMemorySize,
                         (int)smem);
    dim3 fgrid(S_LEN / 64, NH, B_SZ);
    flash_kernel<<<fgrid, 256, smem>>>(q, k, v, attn);

    // Output projection
    gemm_bf16x3<<<ggrid, 256, GEMM_SMEM_BYTES>>>(attn, wot, out, M_TOT, DM, DM);
}

// round 4
// speedup vs baseline: 2.5733x; 1.5717x over previous
#include <cuda_runtime.h>
#include <cuda_bf16.h>
#include <cstdint>
#include <math.h>

#define B_SZ   4
#define S_LEN  2048
#define NH     16
#define HD     128
#define DM     2048
#define M_TOT  (B_SZ * S_LEN)       // 8192 tokens

// Scratch (allocation-free: __device__ globals)
__device__ __align__(128) float g_q[(size_t)M_TOT * DM];
__device__ __align__(128) float g_k[(size_t)M_TOT * DM];
__device__ __align__(128) float g_v[(size_t)M_TOT * DM];
__device__ __align__(128) float g_attn[(size_t)M_TOT * DM];
__device__ __align__(128) float g_wt[4][(size_t)DM * DM];   // transposed weights

// ---------------------------------------------------------------------------
// Common helpers
// ---------------------------------------------------------------------------
__device__ __forceinline__ uint32_t smem_u32(const void* p) {
    uint32_t a;
    asm("{ .reg .u64 t; cvta.to.shared.u64 t, %1; cvt.u32.u64 %0, t; }"
        : "=r"(a) : "l"(p));
    return a;
}

__device__ __forceinline__ uint32_t pack_bf2(__nv_bfloat16 a, __nv_bfloat16 b) {
    __nv_bfloat162 t = __halves2bfloat162(a, b);
    return *reinterpret_cast<uint32_t*>(&t);
}

#define MMA16816(d, a, b)                                                    \
    asm volatile(                                                            \
        "mma.sync.aligned.m16n8k16.row.col.f32.bf16.bf16.f32 "               \
        "{%0,%1,%2,%3}, {%4,%5,%6,%7}, {%8,%9}, {%0,%1,%2,%3};"              \
        : "+f"((d)[0]), "+f"((d)[1]), "+f"((d)[2]), "+f"((d)[3])             \
        : "r"((a)[0]), "r"((a)[1]), "r"((a)[2]), "r"((a)[3]),                \
          "r"((b)[0]), "r"((b)[1]))

#define MMA2(d, a0, a1, a2, a3, b0, b1)                                      \
    asm volatile(                                                            \
        "mma.sync.aligned.m16n8k16.row.col.f32.bf16.bf16.f32 "               \
        "{%0,%1,%2,%3}, {%4,%5,%6,%7}, {%8,%9}, {%0,%1,%2,%3};"              \
        : "+f"((d)[0]), "+f"((d)[1]), "+f"((d)[2]), "+f"((d)[3])             \
        : "r"(a0), "r"(a1), "r"(a2), "r"(a3), "r"(b0), "r"(b1))

#define LDMX4(r0, r1, r2, r3, addr)                                          \
    asm volatile("ldmatrix.sync.aligned.m8n8.x4.shared.b16 "                 \
        "{%0,%1,%2,%3}, [%4];"                                               \
        : "=r"(r0), "=r"(r1), "=r"(r2), "=r"(r3) : "r"(addr))

#define LDMX4T(r0, r1, r2, r3, addr)                                         \
    asm volatile("ldmatrix.sync.aligned.m8n8.x4.trans.shared.b16 "           \
        "{%0,%1,%2,%3}, [%4];"                                               \
        : "=r"(r0), "=r"(r1), "=r"(r2), "=r"(r3) : "r"(addr))

// ---------------------------------------------------------------------------
// Transpose: out[N,K] = in[K,N], 2048x2048
// ---------------------------------------------------------------------------
__global__ __launch_bounds__(256) void transpose2048(
    const float* __restrict__ in, float* __restrict__ out)
{
    __shared__ float t[32][33];
    int x = blockIdx.x * 32 + threadIdx.x;
    int y = blockIdx.y * 32 + threadIdx.y;
    #pragma unroll
    for (int i = 0; i < 4; i++)
        t[threadIdx.y + i * 8][threadIdx.x] = in[(size_t)(y + i * 8) * DM + x];
    __syncthreads();
    x = blockIdx.y * 32 + threadIdx.x;
    y = blockIdx.x * 32 + threadIdx.y;
    #pragma unroll
    for (int i = 0; i < 4; i++)
        out[(size_t)(y + i * 8) * DM + x] = t[threadIdx.x][threadIdx.y + i * 8];
}

// ---------------------------------------------------------------------------
// bf16x3 tensor-core GEMM (unchanged from R3)
// ---------------------------------------------------------------------------
#define KCHUNK  32
#define APAD    40
#define TILE_EL (128 * APAD)
#define GEMM_SMEM_BYTES (2 * 4 * TILE_EL * 2)

__device__ __forceinline__ void cvt_store_pair(
    __nv_bfloat16* __restrict__ H, __nv_bfloat16* __restrict__ L,
    int r, int c4, float4 v)
{
    __nv_bfloat16 hx = __float2bfloat16(v.x);
    __nv_bfloat16 hy = __float2bfloat16(v.y);
    __nv_bfloat16 hz = __float2bfloat16(v.z);
    __nv_bfloat16 hw = __float2bfloat16(v.w);
    __nv_bfloat16 lx = __float2bfloat16(v.x - __bfloat162float(hx));
    __nv_bfloat16 ly = __float2bfloat16(v.y - __bfloat162float(hy));
    __nv_bfloat16 lz = __float2bfloat16(v.z - __bfloat162float(hz));
    __nv_bfloat16 lw = __float2bfloat16(v.w - __bfloat162float(hw));
    int off = r * APAD + c4 * 4;
    *(uint2*)(H + off) = make_uint2(pack_bf2(hx, hy), pack_bf2(hz, hw));
    *(uint2*)(L + off) = make_uint2(pack_bf2(lx, ly), pack_bf2(lz, lw));
}

__global__ __launch_bounds__(256) void gemm_bf16x3(
    const float* __restrict__ A, const float* __restrict__ Bt,
    float* __restrict__ C, int M, int N, int K)
{
    extern __shared__ __align__(16) __nv_bfloat16 sm[];

    const int tid  = threadIdx.x;
    const int lane = tid & 31;
    const int wid  = tid >> 5;
    const int warpM = wid & 1;
    const int warpN = wid >> 1;
    const int n0 = blockIdx.x * 128;
    const int m0 = blockIdx.y * 128;

    const int row_ = tid >> 3;
    const int c_   = tid & 7;
    const float* Ab = A  + (size_t)(m0 + row_) * K + c_ * 4;
    const float* Bb = Bt + (size_t)(n0 + row_) * K + c_ * 4;

    float acc[4][4][4];
    #pragma unroll
    for (int mt = 0; mt < 4; mt++)
        #pragma unroll
        for (int nt = 0; nt < 4; nt++)
            #pragma unroll
            for (int e = 0; e < 4; e++) acc[mt][nt][e] = 0.f;

    float4 ra[4], rb[4];
    #pragma unroll
    for (int i = 0; i < 4; i++) {
        ra[i] = *(const float4*)(Ab + (size_t)(i * 32) * K);
        rb[i] = *(const float4*)(Bb + (size_t)(i * 32) * K);
    }

    const int NK = K / KCHUNK;
    const int mrow = lane >> 2;
    const int kcol = (lane & 3) * 2;

    for (int kt = 0; kt < NK; kt++) {
        const int p = kt & 1;
        __nv_bfloat16* Ah = sm + (size_t)(p * 4 + 0) * TILE_EL;
        __nv_bfloat16* Al = sm + (size_t)(p * 4 + 1) * TILE_EL;
        __nv_bfloat16* Bh = sm + (size_t)(p * 4 + 2) * TILE_EL;
        __nv_bfloat16* Bl = sm + (size_t)(p * 4 + 3) * TILE_EL;

        #pragma unroll
        for (int i = 0; i < 4; i++) {
            cvt_store_pair(Ah, Al, row_ + i * 32, c_, ra[i]);
            cvt_store_pair(Bh, Bl, row_ + i * 32, c_, rb[i]);
        }
        __syncthreads();

        if (kt + 1 < NK) {
            #pragma unroll
            for (int i = 0; i < 4; i++) {
                ra[i] = *(const float4*)(Ab + (size_t)(i * 32) * K + (kt + 1) * KCHUNK);
                rb[i] = *(const float4*)(Bb + (size_t)(i * 32) * K + (kt + 1) * KCHUNK);
            }
        }

        #pragma unroll
        for (int ks = 0; ks < 2; ks++) {
            const int kb = ks * 16 + kcol;
            uint32_t ah[4][4], al[4][4], bh[4][2], bl[4][2];
            #pragma unroll
            for (int mt = 0; mt < 4; mt++) {
                int r = warpM * 64 + mt * 16 + mrow;
                ah[mt][0] = *(const uint32_t*)(Ah + r * APAD + kb);
                ah[mt][1] = *(const uint32_t*)(Ah + (r + 8) * APAD + kb);
                ah[mt][2] = *(const uint32_t*)(Ah + r * APAD + kb + 8);
                ah[mt][3] = *(const uint32_t*)(Ah + (r + 8) * APAD + kb + 8);
                al[mt][0] = *(const uint32_t*)(Al + r * APAD + kb);
                al[mt][1] = *(const uint32_t*)(Al + (r + 8) * APAD + kb);
                al[mt][2] = *(const uint32_t*)(Al + r * APAD + kb + 8);
                al[mt][3] = *(const uint32_t*)(Al + (r + 8) * APAD + kb + 8);
            }
            #pragma unroll
            for (int nt = 0; nt < 4; nt++) {
                int c = warpN * 32 + nt * 8 + mrow;
                bh[nt][0] = *(const uint32_t*)(Bh + c * APAD + kb);
                bh[nt][1] = *(const uint32_t*)(Bh + c * APAD + kb + 8);
                bl[nt][0] = *(const uint32_t*)(Bl + c * APAD + kb);
                bl[nt][1] = *(const uint32_t*)(Bl + c * APAD + kb + 8);
            }
            #pragma unroll
            for (int mt = 0; mt < 4; mt++)
                #pragma unroll
                for (int nt = 0; nt < 4; nt++) {
                    MMA16816(acc[mt][nt], ah[mt], bh[nt]);
                    MMA16816(acc[mt][nt], ah[mt], bl[nt]);
                    MMA16816(acc[mt][nt], al[mt], bh[nt]);
                }
        }
        __syncthreads();
    }

    #pragma unroll
    for (int mt = 0; mt < 4; mt++) {
        #pragma unroll
        for (int nt = 0; nt < 4; nt++) {
            int row = m0 + warpM * 64 + mt * 16 + mrow;
            int col = n0 + warpN * 32 + nt * 8 + kcol;
            *(float2*)(C + (size_t)row * N + col) =
                make_float2(acc[mt][nt][0], acc[mt][nt][1]);
            *(float2*)(C + (size_t)(row + 8) * N + col) =
                make_float2(acc[mt][nt][2], acc[mt][nt][3]);
        }
    }
}

// ---------------------------------------------------------------------------
// LLaMA interleaved RoPE; q additionally scaled by 1/sqrt(H).
// ---------------------------------------------------------------------------
__global__ void rope_kernel(float* __restrict__ q, float* __restrict__ k, int total)
{
    int idx = blockIdx.x * blockDim.x + threadIdx.x;
    if (idx >= total) return;
    int pair = idx & 63;
    int n    = (idx >> 6) & (NH - 1);
    int m    = idx >> 10;
    int s    = m & (S_LEN - 1);

    float fraction  = (2.0f * (float)pair) / (float)HD;
    float timescale = exp2f(fraction * 13.287712379549449f); // log2(10000)
    float ang = (float)s / timescale;
    float sv, cv;
    sincosf(ang, &sv, &cv);

    size_t base = (size_t)m * DM + (size_t)n * HD + pair * 2;
    const float qs = 0.08838834764831845f; // 1/sqrt(128)

    float q1 = q[base], q2 = q[base + 1];
    q[base]     = (q1 * cv - q2 * sv) * qs;
    q[base + 1] = (q2 * cv + q1 * sv) * qs;

    float k1 = k[base], k2 = k[base + 1];
    k[base]     = k1 * cv - k2 * sv;
    k[base + 1] = k2 * cv + k1 * sv;
}

// ---------------------------------------------------------------------------
// Tensor-core causal flash attention (bf16x3 split, FA2-style).
// CTA: (q-tile of 128 rows, head, batch). 8 warps; warp w owns rows
// [w*16, w*16+16). K/V processed in 64-key tiles.
// ---------------------------------------------------------------------------
#define FSTR   136                         // smem row stride (bf16 elems)
#define F_QH   0
#define F_QL   (128 * FSTR)
#define F_KH   (2 * 128 * FSTR)
#define F_KL   (F_KH + 64 * FSTR)
#define F_VH   (F_KL + 64 * FSTR)
#define F_VL   (F_VH + 64 * FSTR)
#define F_TOT_EL (F_VL + 64 * FSTR)        // 69632 elems
#define FLASH_SMEM_BYTES (F_TOT_EL * 2)    // 139264 B

__device__ __forceinline__ void fsplit_store(
    __nv_bfloat16* __restrict__ p, int offH, int offL, float4 v)
{
    __nv_bfloat16 hx = __float2bfloat16(v.x);
    __nv_bfloat16 hy = __float2bfloat16(v.y);
    __nv_bfloat16 hz = __float2bfloat16(v.z);
    __nv_bfloat16 hw = __float2bfloat16(v.w);
    __nv_bfloat16 lx = __float2bfloat16(v.x - __bfloat162float(hx));
    __nv_bfloat16 ly = __float2bfloat16(v.y - __bfloat162float(hy));
    __nv_bfloat16 lz = __float2bfloat16(v.z - __bfloat162float(hz));
    __nv_bfloat16 lw = __float2bfloat16(v.w - __bfloat162float(hw));
    *(uint2*)(p + offH) = make_uint2(pack_bf2(hx, hy), pack_bf2(hz, hw));
    *(uint2*)(p + offL) = make_uint2(pack_bf2(lx, ly), pack_bf2(lz, lw));
}

__global__ __launch_bounds__(256, 1) void flash_tc(
    const float* __restrict__ Q, const float* __restrict__ K,
    const float* __restrict__ V, float* __restrict__ O)
{
    extern __shared__ __align__(16) __nv_bfloat16 fsm[];
    const uint32_t sb = smem_u32(fsm);

    const int tid  = threadIdx.x;
    const int lane = tid & 31;
    const int w    = tid >> 5;
    const int qt   = blockIdx.x;
    const int hN   = blockIdx.y;
    const int b    = blockIdx.z;
    const int q0   = qt * 128;
    const size_t head = (size_t)hN * HD;

    // ---- load Q tile (128x128) with hi/lo split ----
    {
        const int row = tid >> 5;          // constant per warp + 8*i
        const int c4  = lane;
        #pragma unroll
        for (int i = 0; i < 16; i++) {
            int r = row + i * 8;
            size_t g = ((size_t)(b * S_LEN + q0 + r)) * DM + head + c4 * 4;
            float4 v = *(const float4*)(Q + g);
            fsplit_store(fsm, F_QH + r * FSTR + c4 * 4,
                              F_QL + r * FSTR + c4 * 4, v);
        }
    }

    // Running stats (rows r = w*16 + lane>>2 and +8)
    float m0 = -1e30f, m1 = -1e30f, l0 = 0.f, l1 = 0.f;
    float o[16][4];
    #pragma unroll
    for (int t = 0; t < 16; t++)
        #pragma unroll
        for (int e = 0; e < 4; e++) o[t][e] = 0.f;

    const int ktiles = 2 * qt + 2;

    // ldmatrix source addresses (byte offsets within fsm), per-lane
    // Q/A: rows w*16 + (lane&15), col chunk kc*16 + (lane>>4)*8
    const uint32_t qa_base =
        sb + ((w * 16 + (lane & 15)) * FSTR + (lane >> 4) * 8) * 2;
    // K/B: n = tp*16 + (lane>>4)*8 + (lane&7); col kc*16 + ((lane>>3)&1)*8
    const uint32_t kb_row = ((lane >> 4) * 8 + (lane & 7));
    const uint32_t kb_coladd = ((lane >> 3) & 1) * 8;
    // V/B (trans): k = kc*16 + ((lane>>3)&1)*8 + (lane&7); col tp*16+(lane>>4)*8
    const uint32_t vb_rowadd = ((lane >> 3) & 1) * 8 + (lane & 7);
    const uint32_t vb_coladd = (lane >> 4) * 8;

    for (int kt = 0; kt < ktiles; kt++) {
        const int k0 = kt * 64;
        __syncthreads();
        // ---- load K/V tile (64x128) split hi/lo ----
        {
            const int row = tid >> 5;
            const int c4  = lane;
            #pragma unroll
            for (int i = 0; i < 8; i++) {
                int r = row + i * 8;
                size_t g = ((size_t)(b * S_LEN + k0 + r)) * DM + head + c4 * 4;
                float4 kv = *(const float4*)(K + g);
                float4 vv = *(const float4*)(V + g);
                fsplit_store(fsm, F_KH + r * FSTR + c4 * 4,
                                  F_KL + r * FSTR + c4 * 4, kv);
                fsplit_store(fsm, F_VH + r * FSTR + c4 * 4,
                                  F_VL + r * FSTR + c4 * 4, vv);
            }
        }
        __syncthreads();

        // ---- S = Q K^T (128x64 per CTA, m16 x n64 per warp) ----
        float c[8][4];
        #pragma unroll
        for (int t = 0; t < 8; t++)
            #pragma unroll
            for (int e = 0; e < 4; e++) c[t][e] = 0.f;

        #pragma unroll
        for (int kc = 0; kc < 8; kc++) {
            uint32_t ah0, ah1, ah2, ah3, al0, al1, al2, al3;
            uint32_t qaddr = qa_base + kc * 32;   // kc*16 elems * 2B
            LDMX4(ah0, ah1, ah2, ah3, qaddr);
            LDMX4(al0, al1, al2, al3, qaddr + F_QL * 2);
            #pragma unroll
            for (int tp = 0; tp < 4; tp++) {
                uint32_t bh0, bh1, bh2, bh3, bl0, bl1, bl2, bl3;
                uint32_t kaddr = sb +
                    (F_KH + (tp * 16 + kb_row) * FSTR + kc * 16 + kb_coladd) * 2;
                LDMX4(bh0, bh1, bh2, bh3, kaddr);
                LDMX4(bl0, bl1, bl2, bl3, kaddr + (F_KL - F_KH) * 2);
                MMA2(c[2*tp],   ah0, ah1, ah2, ah3, bh0, bh1);
                MMA2(c[2*tp],   ah0, ah1, ah2, ah3, bl0, bl1);
                MMA2(c[2*tp],   al0, al1, al2, al3, bh0, bh1);
                MMA2(c[2*tp+1], ah0, ah1, ah2, ah3, bh2, bh3);
                MMA2(c[2*tp+1], ah0, ah1, ah2, ah3, bl2, bl3);
                MMA2(c[2*tp+1], al0, al1, al2, al3, bh2, bh3);
            }
        }

        // ---- causal mask (only needed on the 2 diagonal tiles) ----
        const int rowg0 = q0 + w * 16 + (lane >> 2);
        if (kt >= 2 * qt) {
            #pragma unroll
            for (int t = 0; t < 8; t++) {
                int colb = k0 + t * 8 + (lane & 3) * 2;
                if (colb     > rowg0)     c[t][0] = -1e30f;
                if (colb + 1 > rowg0)     c[t][1] = -1e30f;
                if (colb     > rowg0 + 8) c[t][2] = -1e30f;
                if (colb + 1 > rowg0 + 8) c[t][3] = -1e30f;
            }
        }

        // ---- online softmax (warp-local; rows replicated over quads) ----
        float mx0 = -1e30f, mx1 = -1e30f;
        #pragma unroll
        for (int t = 0; t < 8; t++) {
            mx0 = fmaxf(mx0, fmaxf(c[t][0], c[t][1]));
            mx1 = fmaxf(mx1, fmaxf(c[t][2], c[t][3]));
        }
        mx0 = fmaxf(mx0, __shfl_xor_sync(0xffffffffu, mx0, 1));
        mx0 = fmaxf(mx0, __shfl_xor_sync(0xffffffffu, mx0, 2));
        mx1 = fmaxf(mx1, __shfl_xor_sync(0xffffffffu, mx1, 1));
        mx1 = fmaxf(mx1, __shfl_xor_sync(0xffffffffu, mx1, 2));
        const float mn0 = fmaxf(m0, mx0);
        const float mn1 = fmaxf(m1, mx1);
        const float sc0 = __expf(m0 - mn0);
        const float sc1 = __expf(m1 - mn1);
        float sum0 = 0.f, sum1 = 0.f;
        #pragma unroll
        for (int t = 0; t < 8; t++) {
            c[t][0] = __expf(c[t][0] - mn0); sum0 += c[t][0];
            c[t][1] = __expf(c[t][1] - mn0); sum0 += c[t][1];
            c[t][2] = __expf(c[t][2] - mn1); sum1 += c[t][2];
            c[t][3] = __expf(c[t][3] - mn1); sum1 += c[t][3];
        }
        sum0 += __shfl_xor_sync(0xffffffffu, sum0, 1);
        sum0 += __shfl_xor_sync(0xffffffffu, sum0, 2);
        sum1 += __shfl_xor_sync(0xffffffffu, sum1, 1);
        sum1 += __shfl_xor_sync(0xffffffffu, sum1, 2);
        m0 = mn0; m1 = mn1;
        l0 = l0 * sc0 + sum0;
        l1 = l1 * sc1 + sum1;
        #pragma unroll
        for (int t = 0; t < 16; t++) {
            o[t][0] *= sc0; o[t][1] *= sc0;
            o[t][2] *= sc1; o[t][3] *= sc1;
        }

        // ---- O += P V  (m16 x n128, k=64) ----
        #pragma unroll
        for (int kc = 0; kc < 4; kc++) {
            // P fragments from S accumulators (hi/lo split)
            uint32_t pah[4], pal[4];
            #pragma unroll
            for (int half = 0; half < 2; half++) {
                const int t = 2 * kc + half;
                __nv_bfloat16 h0 = __float2bfloat16(c[t][0]);
                __nv_bfloat16 h1 = __float2bfloat16(c[t][1]);
                __nv_bfloat16 h2 = __float2bfloat16(c[t][2]);
                __nv_bfloat16 h3 = __float2bfloat16(c[t][3]);
                pah[2*half]   = pack_bf2(h0, h1);
                pah[2*half+1] = pack_bf2(h2, h3);
                pal[2*half]   = pack_bf2(
                    __float2bfloat16(c[t][0] - __bfloat162float(h0)),
                    __float2bfloat16(c[t][1] - __bfloat162float(h1)));
                pal[2*half+1] = pack_bf2(
                    __float2bfloat16(c[t][2] - __bfloat162float(h2)),
                    __float2bfloat16(c[t][3] - __bfloat162float(h3)));
            }
            // order: a0 = tile2kc lo-rows, a1 = tile2kc hi-rows, a2/a3 = tile2kc+1
            uint32_t ah0 = pah[0], ah1 = pah[1], ah2 = pah[2], ah3 = pah[3];
            uint32_t al0 = pal[0], al1 = pal[1], al2 = pal[2], al3 = pal[3];

            #pragma unroll
            for (int tp = 0; tp < 8; tp++) {
                uint32_t vh0, vh1, vh2, vh3, vl0, vl1, vl2, vl3;
                uint32_t vaddr = sb +
                    (F_VH + (kc * 16 + vb_rowadd) * FSTR + tp * 16 + vb_coladd) * 2;
                LDMX4T(vh0, vh1, vh2, vh3, vaddr);
                LDMX4T(vl0, vl1, vl2, vl3, vaddr + (F_VL - F_VH) * 2);
                MMA2(o[2*tp],   ah0, ah1, ah2, ah3, vh0, vh1);
                MMA2(o[2*tp],   ah0, ah1, ah2, ah3, vl0, vl1);
                MMA2(o[2*tp],   al0, al1, al2, al3, vh0, vh1);
                MMA2(o[2*tp+1], ah0, ah1, ah2, ah3, vh2, vh3);
                MMA2(o[2*tp+1], ah0, ah1, ah2, ah3, vl2, vl3);
                MMA2(o[2*tp+1], al0, al1, al2, al3, vh2, vh3);
            }
        }
    }

    // ---- normalize + write ----
    const float inv0 = 1.0f / l0;
    const float inv1 = 1.0f / l1;
    const int rowg = q0 + w * 16 + (lane >> 2);
    #pragma unroll
    for (int t = 0; t < 16; t++) {
        size_t g0 = ((size_t)(b * S_LEN + rowg)) * DM + head + t * 8 + (lane & 3) * 2;
        size_t g1 = g0 + 8 * DM;
        *(float2*)(O + g0) = make_float2(o[t][0] * inv0, o[t][1] * inv0);
        *(float2*)(O + g1) = make_float2(o[t][2] * inv1, o[t][3] * inv1);
    }
}

// ---------------------------------------------------------------------------
extern "C" void kernel_launch(void* const* d_in, const int* in_sizes, int n_in,
                              void* d_out, int out_size)
{
    const float* x  = (const float*)d_in[0];
    const float* wq = (const float*)d_in[1];
    const float* wk = (const float*)d_in[2];
    const float* wv = (const float*)d_in[3];
    const float* wo = (const float*)d_in[4];
    float* out = (float*)d_out;

    float *q, *k, *v, *attn, *wt;
    cudaGetSymbolAddress((void**)&q,    g_q);
    cudaGetSymbolAddress((void**)&k,    g_k);
    cudaGetSymbolAddress((void**)&v,    g_v);
    cudaGetSymbolAddress((void**)&attn, g_attn);
    cudaGetSymbolAddress((void**)&wt,   g_wt);
    float* wqt = wt;
    float* wkt = wt + (size_t)DM * DM;
    float* wvt = wt + 2 * (size_t)DM * DM;
    float* wot = wt + 3 * (size_t)DM * DM;

    dim3 tgrid(DM / 32, DM / 32), tblk(32, 8);
    transpose2048<<<tgrid, tblk>>>(wq, wqt);
    transpose2048<<<tgrid, tblk>>>(wk, wkt);
    transpose2048<<<tgrid, tblk>>>(wv, wvt);
    transpose2048<<<tgrid, tblk>>>(wo, wot);

    cudaFuncSetAttribute(gemm_bf16x3, cudaFuncAttributeMaxDynamicSharedMemorySize,
                         GEMM_SMEM_BYTES);
    dim3 ggrid(DM / 128, M_TOT / 128);
    gemm_bf16x3<<<ggrid, 256, GEMM_SMEM_BYTES>>>(x, wqt, q, M_TOT, DM, DM);
    gemm_bf16x3<<<ggrid, 256, GEMM_SMEM_BYTES>>>(x, wkt, k, M_TOT, DM, DM);
    gemm_bf16x3<<<ggrid, 256, GEMM_SMEM_BYTES>>>(x, wvt, v, M_TOT, DM, DM);

    int total_pairs = M_TOT * NH * (HD / 2);
    rope_kernel<<<(total_pairs + 255) / 256, 256>>>(q, k, total_pairs);

    cudaFuncSetAttribute(flash_tc, cudaFuncAttributeMaxDynamicSharedMemorySize,
                         FLASH_SMEM_BYTES);
    dim3 fgrid(S_LEN / 128, NH, B_SZ);
    flash_tc<<<fgrid, 256, FLASH_SMEM_BYTES>>>(q, k, v, attn);

    gemm_bf16x3<<<ggrid, 256, GEMM_SMEM_BYTES>>>(attn, wot, out, M_TOT, DM, DM);
}

// round 5
// speedup vs baseline: 2.7009x; 1.0496x over previous
#include <cuda_runtime.h>
#include <cuda_bf16.h>
#include <cstdint>
#include <math.h>

#define B_SZ   4
#define S_LEN  2048
#define NH     16
#define HD     128
#define DM     2048
#define M_TOT  (B_SZ * S_LEN)
typedef __nv_bfloat16 bf;

// ---------------- scratch (device globals; allocation-free) ----------------
__device__ __align__(128) bf    g_xh[(size_t)M_TOT * DM];
__device__ __align__(128) bf    g_xl[(size_t)M_TOT * DM];
__device__ __align__(128) float g_qf[(size_t)M_TOT * DM];
__device__ __align__(128) float g_kf[(size_t)M_TOT * DM];
__device__ __align__(128) bf    g_qh[(size_t)M_TOT * DM];
__device__ __align__(128) bf    g_ql[(size_t)M_TOT * DM];
__device__ __align__(128) bf    g_kh[(size_t)M_TOT * DM];
__device__ __align__(128) bf    g_kl[(size_t)M_TOT * DM];
__device__ __align__(128) bf    g_vh[(size_t)M_TOT * DM];
__device__ __align__(128) bf    g_vl[(size_t)M_TOT * DM];
__device__ __align__(128) bf    g_ah[(size_t)M_TOT * DM];
__device__ __align__(128) bf    g_al[(size_t)M_TOT * DM];
__device__ __align__(128) bf    g_wh[4][(size_t)DM * DM];
__device__ __align__(128) bf    g_wl[4][(size_t)DM * DM];

// ---------------- helpers ----------------
__device__ __forceinline__ uint32_t smem_u32(const void* p) {
    uint32_t a;
    asm("{ .reg .u64 t; cvta.to.shared.u64 t, %1; cvt.u32.u64 %0, t; }"
        : "=r"(a) : "l"(p));
    return a;
}
__device__ __forceinline__ uint32_t pack_bf2(bf a, bf b) {
    __nv_bfloat162 t = __halves2bfloat162(a, b);
    return *reinterpret_cast<uint32_t*>(&t);
}
__device__ __forceinline__ void split1(float v, bf& h, bf& l) {
    h = __float2bfloat16(v);
    l = __float2bfloat16(v - __bfloat162float(h));
}

#define MMA2(d, a0, a1, a2, a3, b0, b1)                                      \
    asm volatile(                                                            \
        "mma.sync.aligned.m16n8k16.row.col.f32.bf16.bf16.f32 "               \
        "{%0,%1,%2,%3}, {%4,%5,%6,%7}, {%8,%9}, {%0,%1,%2,%3};"              \
        : "+f"((d)[0]), "+f"((d)[1]), "+f"((d)[2]), "+f"((d)[3])             \
        : "r"(a0), "r"(a1), "r"(a2), "r"(a3), "r"(b0), "r"(b1))

#define LDMX4(r0, r1, r2, r3, addr)                                          \
    asm volatile("ldmatrix.sync.aligned.m8n8.x4.shared.b16 "                 \
        "{%0,%1,%2,%3}, [%4];"                                               \
        : "=r"(r0), "=r"(r1), "=r"(r2), "=r"(r3) : "r"(addr))

#define LDMX4T(r0, r1, r2, r3, addr)                                         \
    asm volatile("ldmatrix.sync.aligned.m8n8.x4.trans.shared.b16 "           \
        "{%0,%1,%2,%3}, [%4];"                                               \
        : "=r"(r0), "=r"(r1), "=r"(r2), "=r"(r3) : "r"(addr))

#define CP16(dst, src)                                                       \
    asm volatile("cp.async.cg.shared.global [%0], [%1], 16;"                 \
                 :: "r"(dst), "l"(src))
#define CP_COMMIT() asm volatile("cp.async.commit_group;" ::)
#define CP_WAIT(n)  asm volatile("cp.async.wait_group %0;" :: "n"(n))

// ---------------------------------------------------------------------------
// convert_split: fp32 -> (hi, lo) bf16, elementwise. 8 elems / thread.
// ---------------------------------------------------------------------------
__global__ __launch_bounds__(256) void convert_split(
    const float* __restrict__ in, bf* __restrict__ H, bf* __restrict__ L)
{
    size_t base = ((size_t)blockIdx.x * 256 + threadIdx.x) * 8;
    #pragma unroll
    for (int j = 0; j < 2; j++) {
        float4 v = *(const float4*)(in + base + j * 4);
        bf hx, hy, hz, hw, lx, ly, lz, lw;
        split1(v.x, hx, lx); split1(v.y, hy, ly);
        split1(v.z, hz, lz); split1(v.w, hw, lw);
        *(uint2*)(H + base + j * 4) = make_uint2(pack_bf2(hx, hy), pack_bf2(hz, hw));
        *(uint2*)(L + base + j * 4) = make_uint2(pack_bf2(lx, ly), pack_bf2(lz, lw));
    }
}

// ---------------------------------------------------------------------------
// transpose_convert: in [K,N] fp32 -> out hi/lo [N,K] bf16
// ---------------------------------------------------------------------------
__global__ __launch_bounds__(256) void transpose_convert(
    const float* __restrict__ in, bf* __restrict__ H, bf* __restrict__ L)
{
    __shared__ float t[32][33];
    int x = blockIdx.x * 32 + threadIdx.x;
    int y = blockIdx.y * 32 + threadIdx.y;
    #pragma unroll
    for (int i = 0; i < 4; i++)
        t[threadIdx.y + i * 8][threadIdx.x] = in[(size_t)(y + i * 8) * DM + x];
    __syncthreads();
    x = blockIdx.y * 32 + threadIdx.x;      // k index
    y = blockIdx.x * 32 + threadIdx.y;      // n index
    #pragma unroll
    for (int i = 0; i < 4; i++) {
        float v = t[threadIdx.x][threadIdx.y + i * 8];
        bf h, l; split1(v, h, l);
        H[(size_t)(y + i * 8) * DM + x] = h;
        L[(size_t)(y + i * 8) * DM + x] = l;
    }
}

// ---------------------------------------------------------------------------
// GEMM v2: C[M,N] = A * B^T, A=(Ah,Al)[M,K], B=(Bh,Bl)[N,K] split bf16.
// 128x128 tile, K-chunk 32, 2-stage cp.async, ldmatrix fragments.
// EPI=0: fp32 C.  EPI=1: split bf16 (Ch, Cl).
// ---------------------------------------------------------------------------
#define GSTR   40
#define GA_EL  (128 * GSTR)                  // 5120 elems per array per stage
#define G_STAGE_BYTES (4 * GA_EL * 2)        // 40960
#define GEMM_SMEM_BYTES (2 * G_STAGE_BYTES)  // 81920

template<int EPI>
__global__ __launch_bounds__(256, 2) void gemm_sp(
    const bf* __restrict__ Ah, const bf* __restrict__ Al,
    const bf* __restrict__ Bh, const bf* __restrict__ Bl,
    float* __restrict__ C, bf* __restrict__ Ch, bf* __restrict__ Cl,
    int M, int N, int K)
{
    extern __shared__ __align__(16) char gsm[];
    const uint32_t sb = smem_u32(gsm);

    const int tid  = threadIdx.x;
    const int lane = tid & 31;
    const int wid  = tid >> 5;
    const int warpM = wid & 1;
    const int warpN = wid >> 1;
    const int n0 = blockIdx.x * 128;
    const int m0 = blockIdx.y * 128;

    const int lm = lane & 15, lh = lane >> 4;
    const int kb_row    = (lane >> 4) * 8 + (lane & 7);
    const int kb_coladd = ((lane >> 3) & 1) * 8;

    float acc[4][4][4];
    #pragma unroll
    for (int mt = 0; mt < 4; mt++)
        #pragma unroll
        for (int nt = 0; nt < 4; nt++)
            #pragma unroll
            for (int e = 0; e < 4; e++) acc[mt][nt][e] = 0.f;

    const int NK = K / 32;

    // loader: 2 chunks of 16B per thread per array per stage
    const int r0c = (tid * 2) >> 2;          // row of first chunk
    const int c0c = (tid * 2) & 3;           // chunk of first

    auto issue_stage = [&](int kt, int st) {
        const uint32_t sbase = sb + st * G_STAGE_BYTES;
        #pragma unroll
        for (int j = 0; j < 2; j++) {
            int idx = tid * 2 + j;
            int row = idx >> 2, ch = idx & 3;
            uint32_t doff = (uint32_t)(row * GSTR + ch * 8) * 2;
            size_t aoff = (size_t)(m0 + row) * K + kt * 32 + ch * 8;
            size_t boff = (size_t)(n0 + row) * K + kt * 32 + ch * 8;
            CP16(sbase + doff,                  Ah + aoff);
            CP16(sbase + GA_EL * 2 + doff,      Al + aoff);
            CP16(sbase + 2 * GA_EL * 2 + doff,  Bh + boff);
            CP16(sbase + 3 * GA_EL * 2 + doff,  Bl + boff);
        }
        CP_COMMIT();
    };

    issue_stage(0, 0);

    for (int kt = 0; kt < NK; kt++) {
        const int st = kt & 1;
        if (kt + 1 < NK) { issue_stage(kt + 1, st ^ 1); CP_WAIT(1); }
        else             { CP_WAIT(0); }
        __syncthreads();

        const uint32_t sbase = sb + st * G_STAGE_BYTES;
        #pragma unroll
        for (int kc = 0; kc < 2; kc++) {
            uint32_t ah[4][4], al[4][4], bh[2][4], bl[2][4];
            #pragma unroll
            for (int mt = 0; mt < 4; mt++) {
                uint32_t aaddr = sbase +
                    (uint32_t)((warpM * 64 + mt * 16 + lm) * GSTR + kc * 16 + lh * 8) * 2;
                LDMX4(ah[mt][0], ah[mt][1], ah[mt][2], ah[mt][3], aaddr);
                LDMX4(al[mt][0], al[mt][1], al[mt][2], al[mt][3], aaddr + GA_EL * 2);
            }
            #pragma unroll
            for (int nt = 0; nt < 2; nt++) {
                uint32_t baddr = sbase + 2 * GA_EL * 2 +
                    (uint32_t)((warpN * 32 + nt * 16 + kb_row) * GSTR + kc * 16 + kb_coladd) * 2;
                LDMX4(bh[nt][0], bh[nt][1], bh[nt][2], bh[nt][3], baddr);
                LDMX4(bl[nt][0], bl[nt][1], bl[nt][2], bl[nt][3], baddr + GA_EL * 2);
            }
            #pragma unroll
            for (int mt = 0; mt < 4; mt++)
                #pragma unroll
                for (int nt = 0; nt < 2; nt++) {
                    MMA2(acc[mt][2*nt],   ah[mt][0], ah[mt][1], ah[mt][2], ah[mt][3], bh[nt][0], bh[nt][1]);
                    MMA2(acc[mt][2*nt],   ah[mt][0], ah[mt][1], ah[mt][2], ah[mt][3], bl[nt][0], bl[nt][1]);
                    MMA2(acc[mt][2*nt],   al[mt][0], al[mt][1], al[mt][2], al[mt][3], bh[nt][0], bh[nt][1]);
                    MMA2(acc[mt][2*nt+1], ah[mt][0], ah[mt][1], ah[mt][2], ah[mt][3], bh[nt][2], bh[nt][3]);
                    MMA2(acc[mt][2*nt+1], ah[mt][0], ah[mt][1], ah[mt][2], ah[mt][3], bl[nt][2], bl[nt][3]);
                    MMA2(acc[mt][2*nt+1], al[mt][0], al[mt][1], al[mt][2], al[mt][3], bh[nt][2], bh[nt][3]);
                }
        }
        __syncthreads();
    }

    const int mrow = lane >> 2;
    const int kcol = (lane & 3) * 2;
    #pragma unroll
    for (int mt = 0; mt < 4; mt++) {
        #pragma unroll
        for (int nt = 0; nt < 4; nt++) {
            int row = m0 + warpM * 64 + mt * 16 + mrow;
            int col = n0 + warpN * 32 + nt * 8 + kcol;
            if (EPI == 0) {
                *(float2*)(C + (size_t)row * N + col) =
                    make_float2(acc[mt][nt][0], acc[mt][nt][1]);
                *(float2*)(C + (size_t)(row + 8) * N + col) =
                    make_float2(acc[mt][nt][2], acc[mt][nt][3]);
            } else {
                bf h0, l0, h1, l1;
                split1(acc[mt][nt][0], h0, l0);
                split1(acc[mt][nt][1], h1, l1);
                *(uint32_t*)(Ch + (size_t)row * N + col) = pack_bf2(h0, h1);
                *(uint32_t*)(Cl + (size_t)row * N + col) = pack_bf2(l0, l1);
                split1(acc[mt][nt][2], h0, l0);
                split1(acc[mt][nt][3], h1, l1);
                *(uint32_t*)(Ch + (size_t)(row + 8) * N + col) = pack_bf2(h0, h1);
                *(uint32_t*)(Cl + (size_t)(row + 8) * N + col) = pack_bf2(l0, l1);
            }
        }
    }
}

// ---------------------------------------------------------------------------
// RoPE on fp32 q,k; writes split bf16. q scaled by 1/sqrt(H).
// ---------------------------------------------------------------------------
__global__ void rope_convert(
    const float* __restrict__ q, const float* __restrict__ k,
    bf* __restrict__ qh, bf* __restrict__ ql,
    bf* __restrict__ kh, bf* __restrict__ kl, int total)
{
    int idx = blockIdx.x * blockDim.x + threadIdx.x;
    if (idx >= total) return;
    int pair = idx & 63;
    int m    = idx >> 10;
    int s    = m & (S_LEN - 1);

    float fraction  = (2.0f * (float)pair) / (float)HD;
    float timescale = exp2f(fraction * 13.287712379549449f);
    float ang = (float)s / timescale;
    float sv, cv;
    sincosf(ang, &sv, &cv);

    size_t base = (size_t)m * DM + (size_t)((idx >> 6) & (NH - 1)) * HD + pair * 2;
    const float qs = 0.08838834764831845f;

    float q1 = q[base], q2 = q[base + 1];
    float r1 = (q1 * cv - q2 * sv) * qs;
    float r2 = (q2 * cv + q1 * sv) * qs;
    bf h1, l1, h2, l2;
    split1(r1, h1, l1); split1(r2, h2, l2);
    *(uint32_t*)(qh + base) = pack_bf2(h1, h2);
    *(uint32_t*)(ql + base) = pack_bf2(l1, l2);

    float k1 = k[base], k2 = k[base + 1];
    r1 = k1 * cv - k2 * sv;
    r2 = k2 * cv + k1 * sv;
    split1(r1, h1, l1); split1(r2, h2, l2);
    *(uint32_t*)(kh + base) = pack_bf2(h1, h2);
    *(uint32_t*)(kl + base) = pack_bf2(l1, l2);
}

// ---------------------------------------------------------------------------
// Flash attention v2: split-bf16 inputs via cp.async, double-buffered K/V.
// CTA: (128-row q tile, head, batch), 8 warps. Output: split bf16 attn.
// ---------------------------------------------------------------------------
#define FSTR    136
#define F_QH    0
#define F_QL    (128 * FSTR)
#define F_KV0   (2 * 128 * FSTR)
#define F_KVSZ  (4 * 64 * FSTR)
#define LO_OFF  (64 * FSTR)
#define FLASH_SMEM_BYTES ((F_KV0 + 2 * F_KVSZ) * 2)   // 208896

__global__ __launch_bounds__(256, 1) void flash_tc2(
    const bf* __restrict__ Qh, const bf* __restrict__ Ql,
    const bf* __restrict__ Kh, const bf* __restrict__ Kl,
    const bf* __restrict__ Vh, const bf* __restrict__ Vl,
    bf* __restrict__ Oh, bf* __restrict__ Ol)
{
    extern __shared__ __align__(16) bf fsm[];
    const uint32_t sb = smem_u32(fsm);

    const int tid  = threadIdx.x;
    const int lane = tid & 31;
    const int w    = tid >> 5;
    const int qt   = blockIdx.x;
    const int hN   = blockIdx.y;
    const int b    = blockIdx.z;
    const int q0   = qt * 128;
    const size_t head = (size_t)hN * HD;

    auto issue_kv = [&](int kt, int st) {
        const int k0 = kt * 64;
        const uint32_t base = sb + (F_KV0 + st * F_KVSZ) * 2;
        #pragma unroll
        for (int i = 0; i < 4; i++) {
            int idx = tid + i * 256;            // 0..1023
            int row = idx >> 4, ch = idx & 15;
            uint32_t doff = (uint32_t)(row * FSTR + ch * 8) * 2;
            size_t g = ((size_t)(b * S_LEN + k0 + row)) * DM + head + ch * 8;
            CP16(base + doff,                    Kh + g);
            CP16(base + LO_OFF * 2 + doff,       Kl + g);
            CP16(base + 2 * LO_OFF * 2 + doff,   Vh + g);
            CP16(base + 3 * LO_OFF * 2 + doff,   Vl + g);
        }
        CP_COMMIT();
    };

    // prologue: Q + KV stage 0 in one group
    #pragma unroll
    for (int i = 0; i < 8; i++) {
        int idx = tid + i * 256;                // 0..2047
        int row = idx >> 4, ch = idx & 15;
        uint32_t doff = (uint32_t)(row * FSTR + ch * 8) * 2;
        size_t g = ((size_t)(b * S_LEN + q0 + row)) * DM + head + ch * 8;
        CP16(sb + doff,              Qh + g);
        CP16(sb + F_QL * 2 + doff,   Ql + g);
    }
    issue_kv(0, 0);   // commits Q + KV0 together

    float m0 = -1e30f, m1 = -1e30f, l0 = 0.f, l1 = 0.f;
    float o[16][4];
    #pragma unroll
    for (int t = 0; t < 16; t++)
        #pragma unroll
        for (int e = 0; e < 4; e++) o[t][e] = 0.f;

    const int ktiles = 2 * qt + 2;

    const uint32_t qa_base =
        sb + ((w * 16 + (lane & 15)) * FSTR + (lane >> 4) * 8) * 2;
    const uint32_t kb_row    = (lane >> 4) * 8 + (lane & 7);
    const uint32_t kb_coladd = ((lane >> 3) & 1) * 8;
    const uint32_t vb_rowadd = ((lane >> 3) & 1) * 8 + (lane & 7);
    const uint32_t vb_coladd = (lane >> 4) * 8;

    for (int kt = 0; kt < ktiles; kt++) {
        const int st = kt & 1;
        if (kt + 1 < ktiles) { issue_kv(kt + 1, st ^ 1); CP_WAIT(1); }
        else                 { CP_WAIT(0); }
        __syncthreads();

        const uint32_t khb = F_KV0 + st * F_KVSZ;
        const uint32_t vhb = khb + 2 * LO_OFF;

        // ---- S = Q K^T ----
        float c[8][4];
        #pragma unroll
        for (int t = 0; t < 8; t++)
            #pragma unroll
            for (int e = 0; e < 4; e++) c[t][e] = 0.f;

        #pragma unroll
        for (int kc = 0; kc < 8; kc++) {
            uint32_t ah0, ah1, ah2, ah3, al0, al1, al2, al3;
            uint32_t qaddr = qa_base + kc * 32;
            LDMX4(ah0, ah1, ah2, ah3, qaddr);
            LDMX4(al0, al1, al2, al3, qaddr + F_QL * 2);
            #pragma unroll
            for (int tp = 0; tp < 4; tp++) {
                uint32_t bh0, bh1, bh2, bh3, bl0, bl1, bl2, bl3;
                uint32_t kaddr = sb +
                    (khb + (tp * 16 + kb_row) * FSTR + kc * 16 + kb_coladd) * 2;
                LDMX4(bh0, bh1, bh2, bh3, kaddr);
                LDMX4(bl0, bl1, bl2, bl3, kaddr + LO_OFF * 2);
                MMA2(c[2*tp],   ah0, ah1, ah2, ah3, bh0, bh1);
                MMA2(c[2*tp],   ah0, ah1, ah2, ah3, bl0, bl1);
                MMA2(c[2*tp],   al0, al1, al2, al3, bh0, bh1);
                MMA2(c[2*tp+1], ah0, ah1, ah2, ah3, bh2, bh3);
                MMA2(c[2*tp+1], ah0, ah1, ah2, ah3, bl2, bl3);
                MMA2(c[2*tp+1], al0, al1, al2, al3, bh2, bh3);
            }
        }

        // ---- causal mask on diagonal tiles ----
        const int rowg0 = q0 + w * 16 + (lane >> 2);
        if (kt >= 2 * qt) {
            const int k0 = kt * 64;
            #pragma unroll
            for (int t = 0; t < 8; t++) {
                int colb = k0 + t * 8 + (lane & 3) * 2;
                if (colb     > rowg0)     c[t][0] = -1e30f;
                if (colb + 1 > rowg0)     c[t][1] = -1e30f;
                if (colb     > rowg0 + 8) c[t][2] = -1e30f;
                if (colb + 1 > rowg0 + 8) c[t][3] = -1e30f;
            }
        }

        // ---- online softmax ----
        float mx0 = -1e30f, mx1 = -1e30f;
        #pragma unroll
        for (int t = 0; t < 8; t++) {
            mx0 = fmaxf(mx0, fmaxf(c[t][0], c[t][1]));
            mx1 = fmaxf(mx1, fmaxf(c[t][2], c[t][3]));
        }
        mx0 = fmaxf(mx0, __shfl_xor_sync(0xffffffffu, mx0, 1));
        mx0 = fmaxf(mx0, __shfl_xor_sync(0xffffffffu, mx0, 2));
        mx1 = fmaxf(mx1, __shfl_xor_sync(0xffffffffu, mx1, 1));
        mx1 = fmaxf(mx1, __shfl_xor_sync(0xffffffffu, mx1, 2));
        const float mn0 = fmaxf(m0, mx0);
        const float mn1 = fmaxf(m1, mx1);
        const float sc0 = __expf(m0 - mn0);
        const float sc1 = __expf(m1 - mn1);
        float sum0 = 0.f, sum1 = 0.f;
        #pragma unroll
        for (int t = 0; t < 8; t++) {
            c[t][0] = __expf(c[t][0] - mn0); sum0 += c[t][0];
            c[t][1] = __expf(c[t][1] - mn0); sum0 += c[t][1];
            c[t][2] = __expf(c[t][2] - mn1); sum1 += c[t][2];
            c[t][3] = __expf(c[t][3] - mn1); sum1 += c[t][3];
        }
        sum0 += __shfl_xor_sync(0xffffffffu, sum0, 1);
        sum0 += __shfl_xor_sync(0xffffffffu, sum0, 2);
        sum1 += __shfl_xor_sync(0xffffffffu, sum1, 1);
        sum1 += __shfl_xor_sync(0xffffffffu, sum1, 2);
        m0 = mn0; m1 = mn1;
        l0 = l0 * sc0 + sum0;
        l1 = l1 * sc1 + sum1;
        #pragma unroll
        for (int t = 0; t < 16; t++) {
            o[t][0] *= sc0; o[t][1] *= sc0;
            o[t][2] *= sc1; o[t][3] *= sc1;
        }

        // ---- O += P V ----
        #pragma unroll
        for (int kc = 0; kc < 4; kc++) {
            uint32_t pah[4], pal[4];
            #pragma unroll
            for (int half = 0; half < 2; half++) {
                const int t = 2 * kc + half;
                bf h0, l0b, h1, l1b, h2, l2b, h3, l3b;
                split1(c[t][0], h0, l0b); split1(c[t][1], h1, l1b);
                split1(c[t][2], h2, l2b); split1(c[t][3], h3, l3b);
                pah[2*half]   = pack_bf2(h0, h1);
                pah[2*half+1] = pack_bf2(h2, h3);
                pal[2*half]   = pack_bf2(l0b, l1b);
                pal[2*half+1] = pack_bf2(l2b, l3b);
            }
            #pragma unroll
            for (int tp = 0; tp < 8; tp++) {
                uint32_t vh0, vh1, vh2, vh3, vl0, vl1, vl2, vl3;
                uint32_t vaddr = sb +
                    (vhb + (kc * 16 + vb_rowadd) * FSTR + tp * 16 + vb_coladd) * 2;
                LDMX4T(vh0, vh1, vh2, vh3, vaddr);
                LDMX4T(vl0, vl1, vl2, vl3, vaddr + LO_OFF * 2);
                MMA2(o[2*tp],   pah[0], pah[1], pah[2], pah[3], vh0, vh1);
                MMA2(o[2*tp],   pah[0], pah[1], pah[2], pah[3], vl0, vl1);
                MMA2(o[2*tp],   pal[0], pal[1], pal[2], pal[3], vh0, vh1);
                MMA2(o[2*tp+1], pah[0], pah[1], pah[2], pah[3], vh2, vh3);
                MMA2(o[2*tp+1], pah[0], pah[1], pah[2], pah[3], vl2, vl3);
                MMA2(o[2*tp+1], pal[0], pal[1], pal[2], pal[3], vh2, vh3);
            }
        }
        __syncthreads();
    }

    // ---- normalize + split-store ----
    const float inv0 = 1.0f / l0;
    const float inv1 = 1.0f / l1;
    const int rowg = q0 + w * 16 + (lane >> 2);
    #pragma unroll
    for (int t = 0; t < 16; t++) {
        size_t g0 = ((size_t)(b * S_LEN + rowg)) * DM + head + t * 8 + (lane & 3) * 2;
        size_t g1 = g0 + 8 * DM;
        bf h0, l0b, h1, l1b;
        split1(o[t][0] * inv0, h0, l0b);
        split1(o[t][1] * inv0, h1, l1b);
        *(uint32_t*)(Oh + g0) = pack_bf2(h0, h1);
        *(uint32_t*)(Ol + g0) = pack_bf2(l0b, l1b);
        split1(o[t][2] * inv1, h0, l0b);
        split1(o[t][3] * inv1, h1, l1b);
        *(uint32_t*)(Oh + g1) = pack_bf2(h0, h1);
        *(uint32_t*)(Ol + g1) = pack_bf2(l0b, l1b);
    }
}

// ---------------------------------------------------------------------------
extern "C" void kernel_launch(void* const* d_in, const int* in_sizes, int n_in,
                              void* d_out, int out_size)
{
    const float* x  = (const float*)d_in[0];
    const float* wq = (const float*)d_in[1];
    const float* wk = (const float*)d_in[2];
    const float* wv = (const float*)d_in[3];
    const float* wo = (const float*)d_in[4];
    float* out = (float*)d_out;

    bf *xh, *xl, *qh, *ql, *kh, *kl, *vh, *vl, *ah, *al, *wh, *wl;
    float *qf, *kf;
    cudaGetSymbolAddress((void**)&xh, g_xh);
    cudaGetSymbolAddress((void**)&xl, g_xl);
    cudaGetSymbolAddress((void**)&qf, g_qf);
    cudaGetSymbolAddress((void**)&kf, g_kf);
    cudaGetSymbolAddress((void**)&qh, g_qh);
    cudaGetSymbolAddress((void**)&ql, g_ql);
    cudaGetSymbolAddress((void**)&kh, g_kh);
    cudaGetSymbolAddress((void**)&kl, g_kl);
    cudaGetSymbolAddress((void**)&vh, g_vh);
    cudaGetSymbolAddress((void**)&vl, g_vl);
    cudaGetSymbolAddress((void**)&ah, g_ah);
    cudaGetSymbolAddress((void**)&al, g_al);
    cudaGetSymbolAddress((void**)&wh, g_wh);
    cudaGetSymbolAddress((void**)&wl, g_wl);
    const size_t WSZ = (size_t)DM * DM;

    // split x; transpose+split weights
    convert_split<<<(M_TOT * (size_t)DM) / (256 * 8), 256>>>(x, xh, xl);
    dim3 tgrid(DM / 32, DM / 32), tblk(32, 8);
    transpose_convert<<<tgrid, tblk>>>(wq, wh + 0 * WSZ, wl + 0 * WSZ);
    transpose_convert<<<tgrid, tblk>>>(wk, wh + 1 * WSZ, wl + 1 * WSZ);
    transpose_convert<<<tgrid, tblk>>>(wv, wh + 2 * WSZ, wl + 2 * WSZ);
    transpose_convert<<<tgrid, tblk>>>(wo, wh + 3 * WSZ, wl + 3 * WSZ);

    cudaFuncSetAttribute(gemm_sp<0>, cudaFuncAttributeMaxDynamicSharedMemorySize,
                         GEMM_SMEM_BYTES);
    cudaFuncSetAttribute(gemm_sp<1>, cudaFuncAttributeMaxDynamicSharedMemorySize,
                         GEMM_SMEM_BYTES);
    dim3 ggrid(DM / 128, M_TOT / 128);
    gemm_sp<0><<<ggrid, 256, GEMM_SMEM_BYTES>>>(xh, xl, wh + 0 * WSZ, wl + 0 * WSZ,
                                                qf, nullptr, nullptr, M_TOT, DM, DM);
    gemm_sp<0><<<ggrid, 256, GEMM_SMEM_BYTES>>>(xh, xl, wh + 1 * WSZ, wl + 1 * WSZ,
                                                kf, nullptr, nullptr, M_TOT, DM, DM);
    gemm_sp<1><<<ggrid, 256, GEMM_SMEM_BYTES>>>(xh, xl, wh + 2 * WSZ, wl + 2 * WSZ,
                                                nullptr, vh, vl, M_TOT, DM, DM);

    int total_pairs = M_TOT * NH * (HD / 2);
    rope_convert<<<(total_pairs + 255) / 256, 256>>>(qf, kf, qh, ql, kh, kl, total_pairs);

    cudaFuncSetAttribute(flash_tc2, cudaFuncAttributeMaxDynamicSharedMemorySize,
                         FLASH_SMEM_BYTES);
    dim3 fgrid(S_LEN / 128, NH, B_SZ);
    flash_tc2<<<fgrid, 256, FLASH_SMEM_BYTES>>>(qh, ql, kh, kl, vh, vl, ah, al);

    gemm_sp<0><<<ggrid, 256, GEMM_SMEM_BYTES>>>(ah, al, wh + 3 * WSZ, wl + 3 * WSZ,
                                                out, nullptr, nullptr, M_TOT, DM, DM);
}

// round 6
// speedup vs baseline: 2.7018x; 1.0003x over previous
#include <cuda_runtime.h>
#include <cuda_bf16.h>
#include <cstdint>
#include <math.h>

#define B_SZ   4
#define S_LEN  2048
#define NH     16
#define HD     128
#define DM     2048
#define M_TOT  (B_SZ * S_LEN)
typedef __nv_bfloat16 bf;

// ---------------- scratch (device globals; allocation-free) ----------------
__device__ __align__(128) bf    g_xh[(size_t)M_TOT * DM];
__device__ __align__(128) bf    g_xl[(size_t)M_TOT * DM];
__device__ __align__(128) float g_qf[(size_t)M_TOT * DM];
__device__ __align__(128) float g_kf[(size_t)M_TOT * DM];
__device__ __align__(128) bf    g_qh[(size_t)M_TOT * DM];
__device__ __align__(128) bf    g_ql[(size_t)M_TOT * DM];
__device__ __align__(128) bf    g_kh[(size_t)M_TOT * DM];
__device__ __align__(128) bf    g_kl[(size_t)M_TOT * DM];
__device__ __align__(128) bf    g_vh[(size_t)M_TOT * DM];
__device__ __align__(128) bf    g_vl[(size_t)M_TOT * DM];
__device__ __align__(128) bf    g_ah[(size_t)M_TOT * DM];
__device__ __align__(128) bf    g_al[(size_t)M_TOT * DM];
__device__ __align__(128) bf    g_wh[4][(size_t)DM * DM];
__device__ __align__(128) bf    g_wl[4][(size_t)DM * DM];

// ---------------- helpers ----------------
__device__ __forceinline__ uint32_t smem_u32(const void* p) {
    uint32_t a;
    asm("{ .reg .u64 t; cvta.to.shared.u64 t, %1; cvt.u32.u64 %0, t; }"
        : "=r"(a) : "l"(p));
    return a;
}
__device__ __forceinline__ uint32_t pack_bf2(bf a, bf b) {
    __nv_bfloat162 t = __halves2bfloat162(a, b);
    return *reinterpret_cast<uint32_t*>(&t);
}
__device__ __forceinline__ void split1(float v, bf& h, bf& l) {
    h = __float2bfloat16(v);
    l = __float2bfloat16(v - __bfloat162float(h));
}

#define MMA2(d, a0, a1, a2, a3, b0, b1)                                      \
    asm volatile(                                                            \
        "mma.sync.aligned.m16n8k16.row.col.f32.bf16.bf16.f32 "               \
        "{%0,%1,%2,%3}, {%4,%5,%6,%7}, {%8,%9}, {%0,%1,%2,%3};"              \
        : "+f"((d)[0]), "+f"((d)[1]), "+f"((d)[2]), "+f"((d)[3])             \
        : "r"(a0), "r"(a1), "r"(a2), "r"(a3), "r"(b0), "r"(b1))

#define LDMX4(r0, r1, r2, r3, addr)                                          \
    asm volatile("ldmatrix.sync.aligned.m8n8.x4.shared.b16 "                 \
        "{%0,%1,%2,%3}, [%4];"                                               \
        : "=r"(r0), "=r"(r1), "=r"(r2), "=r"(r3) : "r"(addr))

#define LDMX4T(r0, r1, r2, r3, addr)                                         \
    asm volatile("ldmatrix.sync.aligned.m8n8.x4.trans.shared.b16 "           \
        "{%0,%1,%2,%3}, [%4];"                                               \
        : "=r"(r0), "=r"(r1), "=r"(r2), "=r"(r3) : "r"(addr))

#define CP16(dst, src)                                                       \
    asm volatile("cp.async.cg.shared.global [%0], [%1], 16;"                 \
                 :: "r"(dst), "l"(src))
#define CP_COMMIT() asm volatile("cp.async.commit_group;" ::)
#define CP_WAIT(n)  asm volatile("cp.async.wait_group %0;" :: "n"(n))

// ---------------------------------------------------------------------------
// convert_split: fp32 -> (hi, lo) bf16, elementwise. 8 elems / thread.
// ---------------------------------------------------------------------------
__global__ __launch_bounds__(256) void convert_split(
    const float* __restrict__ in, bf* __restrict__ H, bf* __restrict__ L)
{
    size_t base = ((size_t)blockIdx.x * 256 + threadIdx.x) * 8;
    #pragma unroll
    for (int j = 0; j < 2; j++) {
        float4 v = *(const float4*)(in + base + j * 4);
        bf hx, hy, hz, hw, lx, ly, lz, lw;
        split1(v.x, hx, lx); split1(v.y, hy, ly);
        split1(v.z, hz, lz); split1(v.w, hw, lw);
        *(uint2*)(H + base + j * 4) = make_uint2(pack_bf2(hx, hy), pack_bf2(hz, hw));
        *(uint2*)(L + base + j * 4) = make_uint2(pack_bf2(lx, ly), pack_bf2(lz, lw));
    }
}

// ---------------------------------------------------------------------------
// transpose_convert: in [K,N] fp32 -> out hi/lo [N,K] bf16
// ---------------------------------------------------------------------------
__global__ __launch_bounds__(256) void transpose_convert(
    const float* __restrict__ in, bf* __restrict__ H, bf* __restrict__ L)
{
    __shared__ float t[32][33];
    int x = blockIdx.x * 32 + threadIdx.x;
    int y = blockIdx.y * 32 + threadIdx.y;
    #pragma unroll
    for (int i = 0; i < 4; i++)
        t[threadIdx.y + i * 8][threadIdx.x] = in[(size_t)(y + i * 8) * DM + x];
    __syncthreads();
    x = blockIdx.y * 32 + threadIdx.x;      // k index
    y = blockIdx.x * 32 + threadIdx.y;      // n index
    #pragma unroll
    for (int i = 0; i < 4; i++) {
        float v = t[threadIdx.x][threadIdx.y + i * 8];
        bf h, l; split1(v, h, l);
        H[(size_t)(y + i * 8) * DM + x] = h;
        L[(size_t)(y + i * 8) * DM + x] = l;
    }
}

// ---------------------------------------------------------------------------
// GEMM v2: C[M,N] = A * B^T, A=(Ah,Al)[M,K], B=(Bh,Bl)[N,K] split bf16.
// 128x128 tile, K-chunk 32, 2-stage cp.async, ldmatrix fragments.
// EPI=0: fp32 C.  EPI=1: split bf16 (Ch, Cl).
// ---------------------------------------------------------------------------
#define GSTR   40
#define GA_EL  (128 * GSTR)                  // 5120 elems per array per stage
#define G_STAGE_BYTES (4 * GA_EL * 2)        // 40960
#define GEMM_SMEM_BYTES (2 * G_STAGE_BYTES)  // 81920

template<int EPI>
__global__ __launch_bounds__(256, 2) void gemm_sp(
    const bf* __restrict__ Ah, const bf* __restrict__ Al,
    const bf* __restrict__ Bh, const bf* __restrict__ Bl,
    float* __restrict__ C, bf* __restrict__ Ch, bf* __restrict__ Cl,
    int M, int N, int K)
{
    extern __shared__ __align__(16) char gsm[];
    const uint32_t sb = smem_u32(gsm);

    const int tid  = threadIdx.x;
    const int lane = tid & 31;
    const int wid  = tid >> 5;
    const int warpM = wid & 1;
    const int warpN = wid >> 1;
    const int n0 = blockIdx.x * 128;
    const int m0 = blockIdx.y * 128;

    const int lm = lane & 15, lh = lane >> 4;
    const int kb_row    = (lane >> 4) * 8 + (lane & 7);
    const int kb_coladd = ((lane >> 3) & 1) * 8;

    float acc[4][4][4];
    #pragma unroll
    for (int mt = 0; mt < 4; mt++)
        #pragma unroll
        for (int nt = 0; nt < 4; nt++)
            #pragma unroll
            for (int e = 0; e < 4; e++) acc[mt][nt][e] = 0.f;

    const int NK = K / 32;

    // loader: 2 chunks of 16B per thread per array per stage
    const int r0c = (tid * 2) >> 2;          // row of first chunk
    const int c0c = (tid * 2) & 3;           // chunk of first

    auto issue_stage = [&](int kt, int st) {
        const uint32_t sbase = sb + st * G_STAGE_BYTES;
        #pragma unroll
        for (int j = 0; j < 2; j++) {
            int idx = tid * 2 + j;
            int row = idx >> 2, ch = idx & 3;
            uint32_t doff = (uint32_t)(row * GSTR + ch * 8) * 2;
            size_t aoff = (size_t)(m0 + row) * K + kt * 32 + ch * 8;
            size_t boff = (size_t)(n0 + row) * K + kt * 32 + ch * 8;
            CP16(sbase + doff,                  Ah + aoff);
            CP16(sbase + GA_EL * 2 + doff,      Al + aoff);
            CP16(sbase + 2 * GA_EL * 2 + doff,  Bh + boff);
            CP16(sbase + 3 * GA_EL * 2 + doff,  Bl + boff);
        }
        CP_COMMIT();
    };

    issue_stage(0, 0);

    for (int kt = 0; kt < NK; kt++) {
        const int st = kt & 1;
        if (kt + 1 < NK) { issue_stage(kt + 1, st ^ 1); CP_WAIT(1); }
        else             { CP_WAIT(0); }
        __syncthreads();

        const uint32_t sbase = sb + st * G_STAGE_BYTES;
        #pragma unroll
        for (int kc = 0; kc < 2; kc++) {
            uint32_t ah[4][4], al[4][4], bh[2][4], bl[2][4];
            #pragma unroll
            for (int mt = 0; mt < 4; mt++) {
                uint32_t aaddr = sbase +
                    (uint32_t)((warpM * 64 + mt * 16 + lm) * GSTR + kc * 16 + lh * 8) * 2;
                LDMX4(ah[mt][0], ah[mt][1], ah[mt][2], ah[mt][3], aaddr);
                LDMX4(al[mt][0], al[mt][1], al[mt][2], al[mt][3], aaddr + GA_EL * 2);
            }
            #pragma unroll
            for (int nt = 0; nt < 2; nt++) {
                uint32_t baddr = sbase + 2 * GA_EL * 2 +
                    (uint32_t)((warpN * 32 + nt * 16 + kb_row) * GSTR + kc * 16 + kb_coladd) * 2;
                LDMX4(bh[nt][0], bh[nt][1], bh[nt][2], bh[nt][3], baddr);
                LDMX4(bl[nt][0], bl[nt][1], bl[nt][2], bl[nt][3], baddr + GA_EL * 2);
            }
            #pragma unroll
            for (int mt = 0; mt < 4; mt++)
                #pragma unroll
                for (int nt = 0; nt < 2; nt++) {
                    MMA2(acc[mt][2*nt],   ah[mt][0], ah[mt][1], ah[mt][2], ah[mt][3], bh[nt][0], bh[nt][1]);
                    MMA2(acc[mt][2*nt],   ah[mt][0], ah[mt][1], ah[mt][2], ah[mt][3], bl[nt][0], bl[nt][1]);
                    MMA2(acc[mt][2*nt],   al[mt][0], al[mt][1], al[mt][2], al[mt][3], bh[nt][0], bh[nt][1]);
                    MMA2(acc[mt][2*nt+1], ah[mt][0], ah[mt][1], ah[mt][2], ah[mt][3], bh[nt][2], bh[nt][3]);
                    MMA2(acc[mt][2*nt+1], ah[mt][0], ah[mt][1], ah[mt][2], ah[mt][3], bl[nt][2], bl[nt][3]);
                    MMA2(acc[mt][2*nt+1], al[mt][0], al[mt][1], al[mt][2], al[mt][3], bh[nt][2], bh[nt][3]);
                }
        }
        __syncthreads();
    }

    const int mrow = lane >> 2;
    const int kcol = (lane & 3) * 2;
    #pragma unroll
    for (int mt = 0; mt < 4; mt++) {
        #pragma unroll
        for (int nt = 0; nt < 4; nt++) {
            int row = m0 + warpM * 64 + mt * 16 + mrow;
            int col = n0 + warpN * 32 + nt * 8 + kcol;
            if (EPI == 0) {
                *(float2*)(C + (size_t)row * N + col) =
                    make_float2(acc[mt][nt][0], acc[mt][nt][1]);
                *(float2*)(C + (size_t)(row + 8) * N + col) =
                    make_float2(acc[mt][nt][2], acc[mt][nt][3]);
            } else {
                bf h0, l0, h1, l1;
                split1(acc[mt][nt][0], h0, l0);
                split1(acc[mt][nt][1], h1, l1);
                *(uint32_t*)(Ch + (size_t)row * N + col) = pack_bf2(h0, h1);
                *(uint32_t*)(Cl + (size_t)row * N + col) = pack_bf2(l0, l1);
                split1(acc[mt][nt][2], h0, l0);
                split1(acc[mt][nt][3], h1, l1);
                *(uint32_t*)(Ch + (size_t)(row + 8) * N + col) = pack_bf2(h0, h1);
                *(uint32_t*)(Cl + (size_t)(row + 8) * N + col) = pack_bf2(l0, l1);
            }
        }
    }
}

// ---------------------------------------------------------------------------
// RoPE on fp32 q,k; writes split bf16. q scaled by 1/sqrt(H).
// ---------------------------------------------------------------------------
__global__ void rope_convert(
    const float* __restrict__ q, const float* __restrict__ k,
    bf* __restrict__ qh, bf* __restrict__ ql,
    bf* __restrict__ kh, bf* __restrict__ kl, int total)
{
    int idx = blockIdx.x * blockDim.x + threadIdx.x;
    if (idx >= total) return;
    int pair = idx & 63;
    int m    = idx >> 10;
    int s    = m & (S_LEN - 1);

    float fraction  = (2.0f * (float)pair) / (float)HD;
    float timescale = exp2f(fraction * 13.287712379549449f);
    float ang = (float)s / timescale;
    float sv, cv;
    sincosf(ang, &sv, &cv);

    size_t base = (size_t)m * DM + (size_t)((idx >> 6) & (NH - 1)) * HD + pair * 2;
    const float qs = 0.08838834764831845f;

    float q1 = q[base], q2 = q[base + 1];
    float r1 = (q1 * cv - q2 * sv) * qs;
    float r2 = (q2 * cv + q1 * sv) * qs;
    bf h1, l1, h2, l2;
    split1(r1, h1, l1); split1(r2, h2, l2);
    *(uint32_t*)(qh + base) = pack_bf2(h1, h2);
    *(uint32_t*)(ql + base) = pack_bf2(l1, l2);

    float k1 = k[base], k2 = k[base + 1];
    r1 = k1 * cv - k2 * sv;
    r2 = k2 * cv + k1 * sv;
    split1(r1, h1, l1); split1(r2, h2, l2);
    *(uint32_t*)(kh + base) = pack_bf2(h1, h2);
    *(uint32_t*)(kl + base) = pack_bf2(l1, l2);
}

// ---------------------------------------------------------------------------
// Flash attention v2: split-bf16 inputs via cp.async, double-buffered K/V.
// CTA: (128-row q tile, head, batch), 8 warps. Output: split bf16 attn.
// ---------------------------------------------------------------------------
#define FSTR    136
#define F_QH    0
#define F_QL    (128 * FSTR)
#define F_KV0   (2 * 128 * FSTR)
#define F_KVSZ  (4 * 64 * FSTR)
#define LO_OFF  (64 * FSTR)
#define FLASH_SMEM_BYTES ((F_KV0 + 2 * F_KVSZ) * 2)   // 208896

__global__ __launch_bounds__(256, 1) void flash_tc2(
    const bf* __restrict__ Qh, const bf* __restrict__ Ql,
    const bf* __restrict__ Kh, const bf* __restrict__ Kl,
    const bf* __restrict__ Vh, const bf* __restrict__ Vl,
    bf* __restrict__ Oh, bf* __restrict__ Ol)
{
    extern __shared__ __align__(16) bf fsm[];
    const uint32_t sb = smem_u32(fsm);

    const int tid  = threadIdx.x;
    const int lane = tid & 31;
    const int w    = tid >> 5;
    const int qt   = blockIdx.x;
    const int hN   = blockIdx.y;
    const int b    = blockIdx.z;
    const int q0   = qt * 128;
    const size_t head = (size_t)hN * HD;

    auto issue_kv = [&](int kt, int st) {
        const int k0 = kt * 64;
        const uint32_t base = sb + (F_KV0 + st * F_KVSZ) * 2;
        #pragma unroll
        for (int i = 0; i < 4; i++) {
            int idx = tid + i * 256;            // 0..1023
            int row = idx >> 4, ch = idx & 15;
            uint32_t doff = (uint32_t)(row * FSTR + ch * 8) * 2;
            size_t g = ((size_t)(b * S_LEN + k0 + row)) * DM + head + ch * 8;
            CP16(base + doff,                    Kh + g);
            CP16(base + LO_OFF * 2 + doff,       Kl + g);
            CP16(base + 2 * LO_OFF * 2 + doff,   Vh + g);
            CP16(base + 3 * LO_OFF * 2 + doff,   Vl + g);
        }
        CP_COMMIT();
    };

    // prologue: Q + KV stage 0 in one group
    #pragma unroll
    for (int i = 0; i < 8; i++) {
        int idx = tid + i * 256;                // 0..2047
        int row = idx >> 4, ch = idx & 15;
        uint32_t doff = (uint32_t)(row * FSTR + ch * 8) * 2;
        size_t g = ((size_t)(b * S_LEN + q0 + row)) * DM + head + ch * 8;
        CP16(sb + doff,              Qh + g);
        CP16(sb + F_QL * 2 + doff,   Ql + g);
    }
    issue_kv(0, 0);   // commits Q + KV0 together

    float m0 = -1e30f, m1 = -1e30f, l0 = 0.f, l1 = 0.f;
    float o[16][4];
    #pragma unroll
    for (int t = 0; t < 16; t++)
        #pragma unroll
        for (int e = 0; e < 4; e++) o[t][e] = 0.f;

    const int ktiles = 2 * qt + 2;

    const uint32_t qa_base =
        sb + ((w * 16 + (lane & 15)) * FSTR + (lane >> 4) * 8) * 2;
    const uint32_t kb_row    = (lane >> 4) * 8 + (lane & 7);
    const uint32_t kb_coladd = ((lane >> 3) & 1) * 8;
    const uint32_t vb_rowadd = ((lane >> 3) & 1) * 8 + (lane & 7);
    const uint32_t vb_coladd = (lane >> 4) * 8;

    for (int kt = 0; kt < ktiles; kt++) {
        const int st = kt & 1;
        if (kt + 1 < ktiles) { issue_kv(kt + 1, st ^ 1); CP_WAIT(1); }
        else                 { CP_WAIT(0); }
        __syncthreads();

        const uint32_t khb = F_KV0 + st * F_KVSZ;
        const uint32_t vhb = khb + 2 * LO_OFF;

        // ---- S = Q K^T ----
        float c[8][4];
        #pragma unroll
        for (int t = 0; t < 8; t++)
            #pragma unroll
            for (int e = 0; e < 4; e++) c[t][e] = 0.f;

        #pragma unroll
        for (int kc = 0; kc < 8; kc++) {
            uint32_t ah0, ah1, ah2, ah3, al0, al1, al2, al3;
            uint32_t qaddr = qa_base + kc * 32;
            LDMX4(ah0, ah1, ah2, ah3, qaddr);
            LDMX4(al0, al1, al2, al3, qaddr + F_QL * 2);
            #pragma unroll
            for (int tp = 0; tp < 4; tp++) {
                uint32_t bh0, bh1, bh2, bh3, bl0, bl1, bl2, bl3;
                uint32_t kaddr = sb +
                    (khb + (tp * 16 + kb_row) * FSTR + kc * 16 + kb_coladd) * 2;
                LDMX4(bh0, bh1, bh2, bh3, kaddr);
                LDMX4(bl0, bl1, bl2, bl3, kaddr + LO_OFF * 2);
                MMA2(c[2*tp],   ah0, ah1, ah2, ah3, bh0, bh1);
                MMA2(c[2*tp],   ah0, ah1, ah2, ah3, bl0, bl1);
                MMA2(c[2*tp],   al0, al1, al2, al3, bh0, bh1);
                MMA2(c[2*tp+1], ah0, ah1, ah2, ah3, bh2, bh3);
                MMA2(c[2*tp+1], ah0, ah1, ah2, ah3, bl2, bl3);
                MMA2(c[2*tp+1], al0, al1, al2, al3, bh2, bh3);
            }
        }

        // ---- causal mask on diagonal tiles ----
        const int rowg0 = q0 + w * 16 + (lane >> 2);
        if (kt >= 2 * qt) {
            const int k0 = kt * 64;
            #pragma unroll
            for (int t = 0; t < 8; t++) {
                int colb = k0 + t * 8 + (lane & 3) * 2;
                if (colb     > rowg0)     c[t][0] = -1e30f;
                if (colb + 1 > rowg0)     c[t][1] = -1e30f;
                if (colb     > rowg0 + 8) c[t][2] = -1e30f;
                if (colb + 1 > rowg0 + 8) c[t][3] = -1e30f;
            }
        }

        // ---- online softmax ----
        float mx0 = -1e30f, mx1 = -1e30f;
        #pragma unroll
        for (int t = 0; t < 8; t++) {
            mx0 = fmaxf(mx0, fmaxf(c[t][0], c[t][1]));
            mx1 = fmaxf(mx1, fmaxf(c[t][2], c[t][3]));
        }
        mx0 = fmaxf(mx0, __shfl_xor_sync(0xffffffffu, mx0, 1));
        mx0 = fmaxf(mx0, __shfl_xor_sync(0xffffffffu, mx0, 2));
        mx1 = fmaxf(mx1, __shfl_xor_sync(0xffffffffu, mx1, 1));
        mx1 = fmaxf(mx1, __shfl_xor_sync(0xffffffffu, mx1, 2));
        const float mn0 = fmaxf(m0, mx0);
        const float mn1 = fmaxf(m1, mx1);
        const float sc0 = __expf(m0 - mn0);
        const float sc1 = __expf(m1 - mn1);
        float sum0 = 0.f, sum1 = 0.f;
        #pragma unroll
        for (int t = 0; t < 8; t++) {
            c[t][0] = __expf(c[t][0] - mn0); sum0 += c[t][0];
            c[t][1] = __expf(c[t][1] - mn0); sum0 += c[t][1];
            c[t][2] = __expf(c[t][2] - mn1); sum1 += c[t][2];
            c[t][3] = __expf(c[t][3] - mn1); sum1 += c[t][3];
        }
        sum0 += __shfl_xor_sync(0xffffffffu, sum0, 1);
        sum0 += __shfl_xor_sync(0xffffffffu, sum0, 2);
        sum1 += __shfl_xor_sync(0xffffffffu, sum1, 1);
        sum1 += __shfl_xor_sync(0xffffffffu, sum1, 2);
        m0 = mn0; m1 = mn1;
        l0 = l0 * sc0 + sum0;
        l1 = l1 * sc1 + sum1;
        #pragma unroll
        for (int t = 0; t < 16; t++) {
            o[t][0] *= sc0; o[t][1] *= sc0;
            o[t][2] *= sc1; o[t][3] *= sc1;
        }

        // ---- O += P V ----
        #pragma unroll
        for (int kc = 0; kc < 4; kc++) {
            uint32_t pah[4], pal[4];
            #pragma unroll
            for (int half = 0; half < 2; half++) {
                const int t = 2 * kc + half;
                bf h0, l0b, h1, l1b, h2, l2b, h3, l3b;
                split1(c[t][0], h0, l0b); split1(c[t][1], h1, l1b);
                split1(c[t][2], h2, l2b); split1(c[t][3], h3, l3b);
                pah[2*half]   = pack_bf2(h0, h1);
                pah[2*half+1] = pack_bf2(h2, h3);
                pal[2*half]   = pack_bf2(l0b, l1b);
                pal[2*half+1] = pack_bf2(l2b, l3b);
            }
            #pragma unroll
            for (int tp = 0; tp < 8; tp++) {
                uint32_t vh0, vh1, vh2, vh3, vl0, vl1, vl2, vl3;
                uint32_t vaddr = sb +
                    (vhb + (kc * 16 + vb_rowadd) * FSTR + tp * 16 + vb_coladd) * 2;
                LDMX4T(vh0, vh1, vh2, vh3, vaddr);
                LDMX4T(vl0, vl1, vl2, vl3, vaddr + LO_OFF * 2);
                MMA2(o[2*tp],   pah[0], pah[1], pah[2], pah[3], vh0, vh1);
                MMA2(o[2*tp],   pah[0], pah[1], pah[2], pah[3], vl0, vl1);
                MMA2(o[2*tp],   pal[0], pal[1], pal[2], pal[3], vh0, vh1);
                MMA2(o[2*tp+1], pah[0], pah[1], pah[2], pah[3], vh2, vh3);
                MMA2(o[2*tp+1], pah[0], pah[1], pah[2], pah[3], vl2, vl3);
                MMA2(o[2*tp+1], pal[0], pal[1], pal[2], pal[3], vh2, vh3);
            }
        }
        __syncthreads();
    }

    // ---- normalize + split-store ----
    const float inv0 = 1.0f / l0;
    const float inv1 = 1.0f / l1;
    const int rowg = q0 + w * 16 + (lane >> 2);
    #pragma unroll
    for (int t = 0; t < 16; t++) {
        size_t g0 = ((size_t)(b * S_LEN + rowg)) * DM + head + t * 8 + (lane & 3) * 2;
        size_t g1 = g0 + 8 * DM;
        bf h0, l0b, h1, l1b;
        split1(o[t][0] * inv0, h0, l0b);
        split1(o[t][1] * inv0, h1, l1b);
        *(uint32_t*)(Oh + g0) = pack_bf2(h0, h1);
        *(uint32_t*)(Ol + g0) = pack_bf2(l0b, l1b);
        split1(o[t][2] * inv1, h0, l0b);
        split1(o[t][3] * inv1, h1, l1b);
        *(uint32_t*)(Oh + g1) = pack_bf2(h0, h1);
        *(uint32_t*)(Ol + g1) = pack_bf2(l0b, l1b);
    }
}

// ---------------------------------------------------------------------------
extern "C" void kernel_launch(void* const* d_in, const int* in_sizes, int n_in,
                              void* d_out, int out_size)
{
    const float* x  = (const float*)d_in[0];
    const float* wq = (const float*)d_in[1];
    const float* wk = (const float*)d_in[2];
    const float* wv = (const float*)d_in[3];
    const float* wo = (const float*)d_in[4];
    float* out = (float*)d_out;

    bf *xh, *xl, *qh, *ql, *kh, *kl, *vh, *vl, *ah, *al, *wh, *wl;
    float *qf, *kf;
    cudaGetSymbolAddress((void**)&xh, g_xh);
    cudaGetSymbolAddress((void**)&xl, g_xl);
    cudaGetSymbolAddress((void**)&qf, g_qf);
    cudaGetSymbolAddress((void**)&kf, g_kf);
    cudaGetSymbolAddress((void**)&qh, g_qh);
    cudaGetSymbolAddress((void**)&ql, g_ql);
    cudaGetSymbolAddress((void**)&kh, g_kh);
    cudaGetSymbolAddress((void**)&kl, g_kl);
    cudaGetSymbolAddress((void**)&vh, g_vh);
    cudaGetSymbolAddress((void**)&vl, g_vl);
    cudaGetSymbolAddress((void**)&ah, g_ah);
    cudaGetSymbolAddress((void**)&al, g_al);
    cudaGetSymbolAddress((void**)&wh, g_wh);
    cudaGetSymbolAddress((void**)&wl, g_wl);
    const size_t WSZ = (size_t)DM * DM;

    // split x; transpose+split weights
    convert_split<<<(M_TOT * (size_t)DM) / (256 * 8), 256>>>(x, xh, xl);
    dim3 tgrid(DM / 32, DM / 32), tblk(32, 8);
    transpose_convert<<<tgrid, tblk>>>(wq, wh + 0 * WSZ, wl + 0 * WSZ);
    transpose_convert<<<tgrid, tblk>>>(wk, wh + 1 * WSZ, wl + 1 * WSZ);
    transpose_convert<<<tgrid, tblk>>>(wv, wh + 2 * WSZ, wl + 2 * WSZ);
    transpose_convert<<<tgrid, tblk>>>(wo, wh + 3 * WSZ, wl + 3 * WSZ);

    cudaFuncSetAttribute(gemm_sp<0>, cudaFuncAttributeMaxDynamicSharedMemorySize,
                         GEMM_SMEM_BYTES);
    cudaFuncSetAttribute(gemm_sp<1>, cudaFuncAttributeMaxDynamicSharedMemorySize,
                         GEMM_SMEM_BYTES);
    dim3 ggrid(DM / 128, M_TOT / 128);
    gemm_sp<0><<<ggrid, 256, GEMM_SMEM_BYTES>>>(xh, xl, wh + 0 * WSZ, wl + 0 * WSZ,
                                                qf, nullptr, nullptr, M_TOT, DM, DM);
    gemm_sp<0><<<ggrid, 256, GEMM_SMEM_BYTES>>>(xh, xl, wh + 1 * WSZ, wl + 1 * WSZ,
                                                kf, nullptr, nullptr, M_TOT, DM, DM);
    gemm_sp<1><<<ggrid, 256, GEMM_SMEM_BYTES>>>(xh, xl, wh + 2 * WSZ, wl + 2 * WSZ,
                                                nullptr, vh, vl, M_TOT, DM, DM);

    int total_pairs = M_TOT * NH * (HD / 2);
    rope_convert<<<(total_pairs + 255) / 256, 256>>>(qf, kf, qh, ql, kh, kl, total_pairs);

    cudaFuncSetAttribute(flash_tc2, cudaFuncAttributeMaxDynamicSharedMemorySize,
                         FLASH_SMEM_BYTES);
    dim3 fgrid(S_LEN / 128, NH, B_SZ);
    flash_tc2<<<fgrid, 256, FLASH_SMEM_BYTES>>>(qh, ql, kh, kl, vh, vl, ah, al);

    gemm_sp<0><<<ggrid, 256, GEMM_SMEM_BYTES>>>(ah, al, wh + 3 * WSZ, wl + 3 * WSZ,
                                                out, nullptr, nullptr, M_TOT, DM, DM);
}